// round 3
// baseline (speedup 1.0000x reference)
#include <cuda_runtime.h>
#include <cstdint>
#include <cstddef>

#define SEQ 4096
#define DM  1024
#define NH  16
#define HD  64
#define NKEY 32
#define NNG 4094

// Scratch (device globals: allocation-free)
__device__ float g_q[SEQ * DM];
__device__ float g_k[SEQ * DM];
__device__ float g_v[SEQ * DM];
__device__ float g_attn[SEQ * DM];
__device__ int   g_idx_is64;

// ---------------------------------------------------------------------------
// idx dtype detector (int64 vs int32, see round 1 notes)
// ---------------------------------------------------------------------------
__global__ void detect_idx_kernel(const int* __restrict__ idx32) {
    g_idx_is64 = ((idx32[1] | idx32[3] | idx32[5] | idx32[7]) == 0) ? 1 : 0;
}

// ---------------------------------------------------------------------------
// TF32 helpers
// ---------------------------------------------------------------------------
__device__ __forceinline__ uint32_t f2tf32(float x) {
    uint32_t r;
    asm("cvt.rna.tf32.f32 %0, %1;" : "=r"(r) : "f"(x));
    return r;
}

__device__ __forceinline__ void mma_tf32(float c[4], const uint32_t a[4], const uint32_t b[2]) {
    asm volatile(
        "mma.sync.aligned.m16n8k8.row.col.f32.tf32.tf32.f32 "
        "{%0,%1,%2,%3}, {%4,%5,%6,%7}, {%8,%9}, {%0,%1,%2,%3};"
        : "+f"(c[0]), "+f"(c[1]), "+f"(c[2]), "+f"(c[3])
        : "r"(a[0]), "r"(a[1]), "r"(a[2]), "r"(a[3]),
          "r"(b[0]), "r"(b[1]));
}

// ---------------------------------------------------------------------------
// TF32 GEMM v2: C[4096,1024] = A[4096,1024] * B[1024,1024].
// 256x128 block tile, BK=8, 512 threads = 16 warps (8x2), warp tile 32x64.
// Double-buffered smem, conflict-free fragment loads (PA=12, PB=136).
// blockIdx.z selects (A,B,C) triple -> fused QKV projection launch.
// ---------------------------------------------------------------------------
#define BM 256
#define BN 128
#define BK 8
#define PA 12
#define PB 136

__global__ __launch_bounds__(512, 1)
void gemm_tf32_kernel(const float* __restrict__ A0, const float* __restrict__ B0, float* __restrict__ C0,
                      const float* __restrict__ A1, const float* __restrict__ B1, float* __restrict__ C1,
                      const float* __restrict__ A2, const float* __restrict__ B2, float* __restrict__ C2) {
    const int N = 1024, K = 1024;
    const float* A = (blockIdx.z == 0) ? A0 : (blockIdx.z == 1) ? A1 : A2;
    const float* B = (blockIdx.z == 0) ? B0 : (blockIdx.z == 1) ? B1 : B2;
    float*       C = (blockIdx.z == 0) ? C0 : (blockIdx.z == 1) ? C1 : C2;

    __shared__ float As[2][BM * PA];     // 24 KB
    __shared__ float Bs[2][BK * PB];     // 8.5 KB

    const int bm = blockIdx.y * BM;
    const int bn = blockIdx.x * BN;
    const int t = threadIdx.x;
    const int lane = t & 31;
    const int warp = t >> 5;
    const int wr = warp >> 1;    // 0..7 (32-row slabs)
    const int wc = warp & 1;     // 0..1 (64-col slabs)

    // staging indices
    const int ar = t >> 1;             // 0..255
    const int akc = (t & 1) << 2;      // 0 or 4
    const int bkr = t >> 5;            // 0..15 (only t<256 used: 0..7)
    const int bcc = (t & 31) << 2;

    float acc[2][8][4];
#pragma unroll
    for (int mi = 0; mi < 2; mi++)
#pragma unroll
        for (int ni = 0; ni < 8; ni++)
#pragma unroll
            for (int e = 0; e < 4; e++) acc[mi][ni][e] = 0.f;

    // ---- prologue: tile 0 -> buffer 0 ----
    {
        float4 v4 = *(const float4*)(A + (size_t)(bm + ar) * K + akc);
        uint32_t c4[4] = { f2tf32(v4.x), f2tf32(v4.y), f2tf32(v4.z), f2tf32(v4.w) };
        *(float4*)&As[0][ar * PA + akc] = *(float4*)c4;
        if (t < 256) {
            float4 w4 = *(const float4*)(B + (size_t)bkr * N + bn + bcc);
            uint32_t d4[4] = { f2tf32(w4.x), f2tf32(w4.y), f2tf32(w4.z), f2tf32(w4.w) };
            *(float4*)&Bs[0][bkr * PB + bcc] = *(float4*)d4;
        }
    }
    __syncthreads();

    const int NT = K / BK;   // 128
#pragma unroll 1
    for (int kt = 0; kt < NT; kt++) {
        const int cur = kt & 1;

        // ---- prefetch next tile (global -> regs) ----
        float4 pa, pb;
        if (kt < NT - 1) {
            const int k0 = (kt + 1) * BK;
            pa = *(const float4*)(A + (size_t)(bm + ar) * K + k0 + akc);
            if (t < 256)
                pb = *(const float4*)(B + (size_t)(k0 + bkr) * N + bn + bcc);
        }

        // ---- compute on current buffer ----
        const uint32_t* as = (const uint32_t*)&As[cur][0];
        const uint32_t* bs = (const uint32_t*)&Bs[cur][0];
        {
            uint32_t af[2][4];
            const int r0 = wr * 32 + (lane >> 2);
            const int ac = lane & 3;
#pragma unroll
            for (int mi = 0; mi < 2; mi++) {
                int r = r0 + mi * 16;
                af[mi][0] = as[r * PA + ac];
                af[mi][1] = as[(r + 8) * PA + ac];
                af[mi][2] = as[r * PA + ac + 4];
                af[mi][3] = as[(r + 8) * PA + ac + 4];
            }
            uint32_t bf[8][2];
            const int kr = lane & 3;
            const int c0 = wc * 64 + (lane >> 2);
#pragma unroll
            for (int ni = 0; ni < 8; ni++) {
                int c = c0 + ni * 8;
                bf[ni][0] = bs[kr * PB + c];
                bf[ni][1] = bs[(kr + 4) * PB + c];
            }
#pragma unroll
            for (int mi = 0; mi < 2; mi++)
#pragma unroll
                for (int ni = 0; ni < 8; ni++)
                    mma_tf32(acc[mi][ni], af[mi], bf[ni]);
        }

        // ---- store prefetched tile into other buffer ----
        if (kt < NT - 1) {
            const int nxt = cur ^ 1;
            uint32_t c4[4] = { f2tf32(pa.x), f2tf32(pa.y), f2tf32(pa.z), f2tf32(pa.w) };
            *(float4*)&As[nxt][ar * PA + akc] = *(float4*)c4;
            if (t < 256) {
                uint32_t d4[4] = { f2tf32(pb.x), f2tf32(pb.y), f2tf32(pb.z), f2tf32(pb.w) };
                *(float4*)&Bs[nxt][bkr * PB + bcc] = *(float4*)d4;
            }
            __syncthreads();
        }
    }

    // ---- epilogue ----
#pragma unroll
    for (int mi = 0; mi < 2; mi++) {
#pragma unroll
        for (int ni = 0; ni < 8; ni++) {
            int r = bm + wr * 32 + mi * 16 + (lane >> 2);
            int c = bn + wc * 64 + ni * 8 + ((lane & 3) << 1);
            float2 v0 = make_float2(acc[mi][ni][0], acc[mi][ni][1]);
            float2 v1 = make_float2(acc[mi][ni][2], acc[mi][ni][3]);
            *(float2*)(C + (size_t)r * N + c) = v0;
            *(float2*)(C + (size_t)(r + 8) * N + c) = v1;
        }
    }
}

// ---------------------------------------------------------------------------
// Sparse attention v2: block = 8 adjacent queries x 2 heads (16 warps).
// Sliding-window keys (lanes 9..31, rows p+lane-20 clipped) are staged once
// per block in smem (30-row union); random keys (lanes 1..8) + global key
// (lane 0) read straight from L2. Window/global indices are reconstructed
// analytically; only random lanes touch idx.
// ---------------------------------------------------------------------------
#define TQ 8
#define WROWS 30

__global__ __launch_bounds__(512)
void sparse_attn_kernel(const float* __restrict__ qb, const float* __restrict__ kb,
                        const float* __restrict__ vb, const void* __restrict__ idxp,
                        float* __restrict__ ob) {
    __shared__ float sQ[TQ][128];
    __shared__ float sK[WROWS][128];
    __shared__ float sV[WROWS][128];

    const int t = threadIdx.x;
    const int pbase = blockIdx.x * TQ + 1;        // first query position
    const int hb = blockIdx.y * 128;              // dim offset of 2-head group
    const int r0 = pbase - 11;                    // window union start row

    // stage Q (8 rows x 128 dims)
    if (t < 256) {
        int row = t >> 5, i = (t & 31) << 2;
        int p = pbase + row;
        if (p <= SEQ - 2)
            *(float4*)&sQ[row][i] = *(const float4*)(qb + (size_t)p * DM + hb + i);
    }
    // stage K/V window union (30 rows x 128 dims each)
#pragma unroll
    for (int f = 0; f < 2 * WROWS * 32; f += 512) {
        int g = f + t;
        if (g < 2 * WROWS * 32) {
            int sel = (g >= WROWS * 32);
            int rem = sel ? g - WROWS * 32 : g;
            int row = rem >> 5, i = (rem & 31) << 2;
            int rg = r0 + row;
            rg = rg < 0 ? 0 : (rg > SEQ - 1 ? SEQ - 1 : rg);
            const float* src = (sel ? vb : kb) + (size_t)rg * DM + hb + i;
            float* dst = (sel ? &sV[0][0] : &sK[0][0]) + row * 128 + i;
            *(float4*)dst = *(const float4*)src;
        }
    }
    __syncthreads();

    const int warp = t >> 5, lane = t & 31;
    const int ql = warp & 7, hl = warp >> 3;
    const int p = pbase + ql;
    if (p > SEQ - 2) return;
    const int n = p - 1;
    const int hdim = hb + hl * 64;

    // per-lane key pointers (generic: smem for window, global otherwise)
    const float* kp;
    const float* vp;
    if (lane >= 9) {
        int rl = ql + lane - 9;     // in [0, 29]
        kp = &sK[rl][hl * 64];
        vp = &sV[rl][hl * 64];
    } else {
        int row = 0;
        if (lane >= 1) {
            row = g_idx_is64
                ? (int)((const long long*)idxp)[(size_t)n * NKEY + lane]
                : ((const int*)idxp)[(size_t)n * NKEY + lane];
        }
        kp = kb + (size_t)row * DM + hdim;
        vp = vb + (size_t)row * DM + hdim;
    }
    const float* qp = &sQ[ql][hl * 64];

    float a = 0.f;
#pragma unroll
    for (int c = 0; c < 16; c++) {
        float4 kv = ((const float4*)kp)[c];
        float4 qv = ((const float4*)qp)[c];
        a += kv.x * qv.x + kv.y * qv.y + kv.z * qv.z + kv.w * qv.w;
    }
    float logit = a * 0.125f;

    // warp softmax over 32 keys
    float m = logit;
#pragma unroll
    for (int o = 16; o > 0; o >>= 1) m = fmaxf(m, __shfl_xor_sync(0xFFFFFFFFu, m, o));
    float e = __expf(logit - m);
    float s = e;
#pragma unroll
    for (int o = 16; o > 0; o >>= 1) s += __shfl_xor_sync(0xFFFFFFFFu, s, o);
    const float prob = e / s;

    // P * V: broadcast (prob_j, vptr_j) from lane j; lanes cover 64 dims
    unsigned long long vpu = (unsigned long long)(uintptr_t)vp;
    float o0 = 0.f, o1 = 0.f;
#pragma unroll
    for (int j = 0; j < NKEY; j++) {
        float pj = __shfl_sync(0xFFFFFFFFu, prob, j);
        unsigned long long up = __shfl_sync(0xFFFFFFFFu, vpu, j);
        const float* vr = (const float*)(uintptr_t)up;
        o0 += pj * vr[lane];
        o1 += pj * vr[lane + 32];
    }
    ob[(size_t)p * DM + hdim + lane] = o0;
    ob[(size_t)p * DM + hdim + 32 + lane] = o1;
}

// ---------------------------------------------------------------------------
// Global attention: positions {0, S-1}, full softmax over all S keys.
// ---------------------------------------------------------------------------
__global__ __launch_bounds__(256)
void global_attn_kernel(const float* __restrict__ qb, const float* __restrict__ kb,
                        const float* __restrict__ vb, float* __restrict__ ob) {
    __shared__ float lg[SEQ];
    __shared__ float qsh[HD];
    __shared__ float red[256];

    const int h = blockIdx.x & (NH - 1);
    const int p = (blockIdx.x >> 4) ? (SEQ - 1) : 0;
    const int t = threadIdx.x;

    if (t < HD / 4)
        ((float4*)qsh)[t] = *(const float4*)(qb + (size_t)p * DM + h * HD + t * 4);
    __syncthreads();

    float lmax = -1e30f;
    for (int j = t; j < SEQ; j += 256) {
        const float* kr = kb + (size_t)j * DM + h * HD;
        float a = 0.f;
#pragma unroll
        for (int c = 0; c < 16; c++) {
            float4 kv = ((const float4*)kr)[c];
            float4 qv = ((const float4*)qsh)[c];
            a += kv.x * qv.x + kv.y * qv.y + kv.z * qv.z + kv.w * qv.w;
        }
        a *= 0.125f;
        lg[j] = a;
        lmax = fmaxf(lmax, a);
    }
    red[t] = lmax; __syncthreads();
    for (int o = 128; o > 0; o >>= 1) {
        if (t < o) red[t] = fmaxf(red[t], red[t + o]);
        __syncthreads();
    }
    const float Mx = red[0];
    __syncthreads();

    float ss = 0.f;
    for (int j = t; j < SEQ; j += 256) {
        float e = __expf(lg[j] - Mx);
        lg[j] = e;
        ss += e;
    }
    red[t] = ss; __syncthreads();
    for (int o = 128; o > 0; o >>= 1) {
        if (t < o) red[t] += red[t + o];
        __syncthreads();
    }
    const float inv = 1.f / red[0];
    __syncthreads();

    const int d = t & (HD - 1);
    const int part = t >> 6;
    float o = 0.f;
    for (int j = part; j < SEQ; j += 4)
        o += lg[j] * vb[(size_t)j * DM + h * HD + d];
    red[t] = o; __syncthreads();
    if (t < HD) {
        float r = (red[t] + red[t + 64] + red[t + 128] + red[t + 192]) * inv;
        ob[(size_t)p * DM + h * HD + t] = r;
    }
}

// ---------------------------------------------------------------------------
// Launch
// ---------------------------------------------------------------------------
extern "C" void kernel_launch(void* const* d_in, const int* in_sizes, int n_in,
                              void* d_out, int out_size) {
    const float* Q  = (const float*)d_in[0];
    const float* K  = (const float*)d_in[1];
    const float* V  = (const float*)d_in[2];
    const float* Wq = (const float*)d_in[3];
    const float* Wk = (const float*)d_in[4];
    const float* Wv = (const float*)d_in[5];
    const float* Wo = (const float*)d_in[6];
    const void*  idx = d_in[7];
    float* out = (float*)d_out;

    float *q, *k, *v, *attn;
    cudaGetSymbolAddress((void**)&q,    g_q);
    cudaGetSymbolAddress((void**)&k,    g_k);
    cudaGetSymbolAddress((void**)&v,    g_v);
    cudaGetSymbolAddress((void**)&attn, g_attn);

    detect_idx_kernel<<<1, 1>>>((const int*)idx);

    // fused Q/K/V projections (z selects operand triple)
    dim3 gqkv(DM / BN, SEQ / BM, 3);   // (8, 16, 3)
    gemm_tf32_kernel<<<gqkv, 512>>>(Q, Wq, q, K, Wk, k, V, Wv, v);

    dim3 gsp((NNG + TQ - 1) / TQ, NH / 2);   // (512, 8)
    sparse_attn_kernel<<<gsp, 512>>>(q, k, v, idx, attn);
    global_attn_kernel<<<2 * NH, 256>>>(q, k, v, attn);

    dim3 go(DM / BN, SEQ / BM, 1);     // (8, 16)
    gemm_tf32_kernel<<<go, 512>>>(attn, Wo, out, attn, Wo, out, attn, Wo, out);
}

// round 4
// speedup vs baseline: 1.0310x; 1.0310x over previous
#include <cuda_runtime.h>
#include <cstdint>
#include <cstddef>

#define SEQ 4096
#define DM  1024
#define NH  16
#define HD  64
#define NKEY 32
#define NNG 4094

// Scratch (device globals: allocation-free)
__device__ float g_q[SEQ * DM];
__device__ float g_k[SEQ * DM];
__device__ float g_v[SEQ * DM];
__device__ float g_attn[SEQ * DM];
__device__ int   g_idx_is64;

// global-attention split-KV partials: 32 (p,h) pairs x 32 chunks
#define GCH 32
__device__ float g_pm[32][GCH];
__device__ float g_ps[32][GCH];
__device__ float g_po[32][GCH][HD];

// ---------------------------------------------------------------------------
// idx dtype detector (int64 vs int32): hi-words of int64 values < 4096 are 0;
// int32 words 1,3,5,7 are randint(1,S) -> never 0.
// ---------------------------------------------------------------------------
__global__ void detect_idx_kernel(const int* __restrict__ idx32) {
    g_idx_is64 = ((idx32[1] | idx32[3] | idx32[5] | idx32[7]) == 0) ? 1 : 0;
}

// ---------------------------------------------------------------------------
// TF32 helpers
// ---------------------------------------------------------------------------
__device__ __forceinline__ uint32_t f2tf32(float x) {
    uint32_t r;
    asm("cvt.rna.tf32.f32 %0, %1;" : "=r"(r) : "f"(x));
    return r;
}

__device__ __forceinline__ void mma_tf32(float c[4], const uint32_t a[4], const uint32_t b[2]) {
    asm volatile(
        "mma.sync.aligned.m16n8k8.row.col.f32.tf32.tf32.f32 "
        "{%0,%1,%2,%3}, {%4,%5,%6,%7}, {%8,%9}, {%0,%1,%2,%3};"
        : "+f"(c[0]), "+f"(c[1]), "+f"(c[2]), "+f"(c[3])
        : "r"(a[0]), "r"(a[1]), "r"(a[2]), "r"(a[3]),
          "r"(b[0]), "r"(b[1]));
}

// ---------------------------------------------------------------------------
// TF32 GEMM v3: C[4096,1024] = A[4096,1024] * B[1024,1024].
// 128x128 block tile, BK=16, 512 threads = 16 warps (4x4), warp tile 32x32.
// acc = 32 regs/thread -> no spills at 512 thr. Double-buffered smem.
// blockIdx.z selects (A,B,C) triple for the fused QKV launch.
// ---------------------------------------------------------------------------
#define BM 128
#define BN 128
#define BK 16
#define PA 20
#define PB 136

__global__ __launch_bounds__(512, 1)
void gemm_tf32_kernel(const float* __restrict__ A0, const float* __restrict__ B0, float* __restrict__ C0,
                      const float* __restrict__ A1, const float* __restrict__ B1, float* __restrict__ C1,
                      const float* __restrict__ A2, const float* __restrict__ B2, float* __restrict__ C2) {
    const int N = 1024, K = 1024;
    const float* A = (blockIdx.z == 0) ? A0 : (blockIdx.z == 1) ? A1 : A2;
    const float* B = (blockIdx.z == 0) ? B0 : (blockIdx.z == 1) ? B1 : B2;
    float*       C = (blockIdx.z == 0) ? C0 : (blockIdx.z == 1) ? C1 : C2;

    __shared__ float As[2][BM * PA];     // 20.5 KB
    __shared__ float Bs[2][BK * PB];     // 17.4 KB

    const int bm = blockIdx.y * BM;
    const int bn = blockIdx.x * BN;
    const int t = threadIdx.x;
    const int lane = t & 31;
    const int warp = t >> 5;
    const int wr = warp >> 2;    // 0..3 (32-row slabs)
    const int wc = warp & 3;     // 0..3 (32-col slabs)

    // staging indices: 512 threads, 1 float4 of A + 1 float4 of B each
    const int ar  = t >> 2;            // 0..127
    const int akc = (t & 3) << 2;      // 0,4,8,12
    const int bkr = t >> 5;            // 0..15
    const int bcc = (t & 31) << 2;     // 0..124

    float acc[2][4][4];
#pragma unroll
    for (int mi = 0; mi < 2; mi++)
#pragma unroll
        for (int ni = 0; ni < 4; ni++)
#pragma unroll
            for (int e = 0; e < 4; e++) acc[mi][ni][e] = 0.f;

    // ---- prologue: tile 0 -> buffer 0 ----
    {
        float4 v4 = *(const float4*)(A + (size_t)(bm + ar) * K + akc);
        uint32_t c4[4] = { f2tf32(v4.x), f2tf32(v4.y), f2tf32(v4.z), f2tf32(v4.w) };
        *(float4*)&As[0][ar * PA + akc] = *(float4*)c4;
        float4 w4 = *(const float4*)(B + (size_t)bkr * N + bn + bcc);
        uint32_t d4[4] = { f2tf32(w4.x), f2tf32(w4.y), f2tf32(w4.z), f2tf32(w4.w) };
        *(float4*)&Bs[0][bkr * PB + bcc] = *(float4*)d4;
    }
    __syncthreads();

    const int NT = K / BK;   // 64
#pragma unroll 1
    for (int kt = 0; kt < NT; kt++) {
        const int cur = kt & 1;

        // ---- prefetch next tile (global -> regs) ----
        float4 pa, pb;
        if (kt < NT - 1) {
            const int k0 = (kt + 1) * BK;
            pa = *(const float4*)(A + (size_t)(bm + ar) * K + k0 + akc);
            pb = *(const float4*)(B + (size_t)(k0 + bkr) * N + bn + bcc);
        }

        // ---- compute on current buffer ----
        const uint32_t* as = (const uint32_t*)&As[cur][0];
        const uint32_t* bs = (const uint32_t*)&Bs[cur][0];
#pragma unroll
        for (int kk = 0; kk < BK; kk += 8) {
            uint32_t af[2][4];
            const int r0 = wr * 32 + (lane >> 2);
            const int ac = kk + (lane & 3);
#pragma unroll
            for (int mi = 0; mi < 2; mi++) {
                int r = r0 + mi * 16;
                af[mi][0] = as[r * PA + ac];
                af[mi][1] = as[(r + 8) * PA + ac];
                af[mi][2] = as[r * PA + ac + 4];
                af[mi][3] = as[(r + 8) * PA + ac + 4];
            }
            uint32_t bf[4][2];
            const int kr = kk + (lane & 3);
            const int c0 = wc * 32 + (lane >> 2);
#pragma unroll
            for (int ni = 0; ni < 4; ni++) {
                int c = c0 + ni * 8;
                bf[ni][0] = bs[kr * PB + c];
                bf[ni][1] = bs[(kr + 4) * PB + c];
            }
#pragma unroll
            for (int mi = 0; mi < 2; mi++)
#pragma unroll
                for (int ni = 0; ni < 4; ni++)
                    mma_tf32(acc[mi][ni], af[mi], bf[ni]);
        }

        // ---- store prefetched tile into other buffer ----
        if (kt < NT - 1) {
            const int nxt = cur ^ 1;
            uint32_t c4[4] = { f2tf32(pa.x), f2tf32(pa.y), f2tf32(pa.z), f2tf32(pa.w) };
            *(float4*)&As[nxt][ar * PA + akc] = *(float4*)c4;
            uint32_t d4[4] = { f2tf32(pb.x), f2tf32(pb.y), f2tf32(pb.z), f2tf32(pb.w) };
            *(float4*)&Bs[nxt][bkr * PB + bcc] = *(float4*)d4;
            __syncthreads();
        }
    }

    // ---- epilogue ----
#pragma unroll
    for (int mi = 0; mi < 2; mi++) {
#pragma unroll
        for (int ni = 0; ni < 4; ni++) {
            int r = bm + wr * 32 + mi * 16 + (lane >> 2);
            int c = bn + wc * 32 + ni * 8 + ((lane & 3) << 1);
            float2 v0 = make_float2(acc[mi][ni][0], acc[mi][ni][1]);
            float2 v1 = make_float2(acc[mi][ni][2], acc[mi][ni][3]);
            *(float2*)(C + (size_t)r * N + c) = v0;
            *(float2*)(C + (size_t)(r + 8) * N + c) = v1;
        }
    }
}

// ---------------------------------------------------------------------------
// Sparse attention: block = 8 adjacent queries x 2 heads (16 warps).
// Window keys staged in smem; random/global keys from L2.
// ---------------------------------------------------------------------------
#define TQ 8
#define WROWS 30

__global__ __launch_bounds__(512)
void sparse_attn_kernel(const float* __restrict__ qb, const float* __restrict__ kb,
                        const float* __restrict__ vb, const void* __restrict__ idxp,
                        float* __restrict__ ob) {
    __shared__ float sQ[TQ][128];
    __shared__ float sK[WROWS][128];
    __shared__ float sV[WROWS][128];

    const int t = threadIdx.x;
    const int pbase = blockIdx.x * TQ + 1;
    const int hb = blockIdx.y * 128;
    const int r0 = pbase - 11;

    if (t < 256) {
        int row = t >> 5, i = (t & 31) << 2;
        int p = pbase + row;
        if (p <= SEQ - 2)
            *(float4*)&sQ[row][i] = *(const float4*)(qb + (size_t)p * DM + hb + i);
    }
#pragma unroll
    for (int f = 0; f < 2 * WROWS * 32; f += 512) {
        int g = f + t;
        if (g < 2 * WROWS * 32) {
            int sel = (g >= WROWS * 32);
            int rem = sel ? g - WROWS * 32 : g;
            int row = rem >> 5, i = (rem & 31) << 2;
            int rg = r0 + row;
            rg = rg < 0 ? 0 : (rg > SEQ - 1 ? SEQ - 1 : rg);
            const float* src = (sel ? vb : kb) + (size_t)rg * DM + hb + i;
            float* dst = (sel ? &sV[0][0] : &sK[0][0]) + row * 128 + i;
            *(float4*)dst = *(const float4*)src;
        }
    }
    __syncthreads();

    const int warp = t >> 5, lane = t & 31;
    const int ql = warp & 7, hl = warp >> 3;
    const int p = pbase + ql;
    if (p > SEQ - 2) return;
    const int n = p - 1;
    const int hdim = hb + hl * 64;

    const float* kp;
    const float* vp;
    if (lane >= 9) {
        int rl = ql + lane - 9;
        kp = &sK[rl][hl * 64];
        vp = &sV[rl][hl * 64];
    } else {
        int row = 0;
        if (lane >= 1) {
            row = g_idx_is64
                ? (int)((const long long*)idxp)[(size_t)n * NKEY + lane]
                : ((const int*)idxp)[(size_t)n * NKEY + lane];
        }
        kp = kb + (size_t)row * DM + hdim;
        vp = vb + (size_t)row * DM + hdim;
    }
    const float* qp = &sQ[ql][hl * 64];

    float a = 0.f;
#pragma unroll
    for (int c = 0; c < 16; c++) {
        float4 kv = ((const float4*)kp)[c];
        float4 qv = ((const float4*)qp)[c];
        a += kv.x * qv.x + kv.y * qv.y + kv.z * qv.z + kv.w * qv.w;
    }
    float logit = a * 0.125f;

    float m = logit;
#pragma unroll
    for (int o = 16; o > 0; o >>= 1) m = fmaxf(m, __shfl_xor_sync(0xFFFFFFFFu, m, o));
    float e = __expf(logit - m);
    float s = e;
#pragma unroll
    for (int o = 16; o > 0; o >>= 1) s += __shfl_xor_sync(0xFFFFFFFFu, s, o);
    const float prob = e / s;

    unsigned long long vpu = (unsigned long long)(uintptr_t)vp;
    float o0 = 0.f, o1 = 0.f;
#pragma unroll
    for (int j = 0; j < NKEY; j++) {
        float pj = __shfl_sync(0xFFFFFFFFu, prob, j);
        unsigned long long up = __shfl_sync(0xFFFFFFFFu, vpu, j);
        const float* vr = (const float*)(uintptr_t)up;
        o0 += pj * vr[lane];
        o1 += pj * vr[lane + 32];
    }
    ob[(size_t)p * DM + hdim + lane] = o0;
    ob[(size_t)p * DM + hdim + 32 + lane] = o1;
}

// ---------------------------------------------------------------------------
// Global attention, split-KV.
// Pass 1: grid (GCH chunks, 32 ph), 128 threads. Each block does a 128-key
//         partial softmax for one (position, head): writes (m, s, o[64]).
// Pass 2: grid 32 blocks, 64 threads: merge the GCH partials.
// ---------------------------------------------------------------------------
__global__ __launch_bounds__(128)
void global_attn_part_kernel(const float* __restrict__ qb, const float* __restrict__ kb,
                             const float* __restrict__ vb) {
    __shared__ float qsh[HD];
    __shared__ float le[128];
    __shared__ float red[128];

    const int c = blockIdx.x;          // key chunk
    const int ph = blockIdx.y;         // 0..31
    const int h = ph & (NH - 1);
    const int p = (ph >> 4) ? (SEQ - 1) : 0;
    const int t = threadIdx.x;
    const int j0 = c * 128;

    if (t < HD / 4)
        ((float4*)qsh)[t] = *(const float4*)(qb + (size_t)p * DM + h * HD + t * 4);
    __syncthreads();

    // logit for key j0 + t
    const float* kr = kb + (size_t)(j0 + t) * DM + h * HD;
    float a = 0.f;
#pragma unroll
    for (int cc = 0; cc < 16; cc++) {
        float4 kv = ((const float4*)kr)[cc];
        float4 qv = ((const float4*)qsh)[cc];
        a += kv.x * qv.x + kv.y * qv.y + kv.z * qv.z + kv.w * qv.w;
    }
    float logit = a * 0.125f;

    // block max
    red[t] = logit; __syncthreads();
#pragma unroll
    for (int o = 64; o > 0; o >>= 1) {
        if (t < o) red[t] = fmaxf(red[t], red[t + o]);
        __syncthreads();
    }
    const float m = red[0];
    __syncthreads();

    float e = __expf(logit - m);
    le[t] = e;
    red[t] = e; __syncthreads();
#pragma unroll
    for (int o = 64; o > 0; o >>= 1) {
        if (t < o) red[t] += red[t + o];
        __syncthreads();
    }
    const float s = red[0];
    __syncthreads();

    // partial o[d] (unnormalized): d = t&63, half = t>>6
    const int d = t & (HD - 1);
    const int half = t >> 6;
    float o = 0.f;
#pragma unroll 4
    for (int j = half * 64; j < half * 64 + 64; j++)
        o += le[j] * vb[(size_t)(j0 + j) * DM + h * HD + d];
    red[t] = o; __syncthreads();
    if (t < HD)
        g_po[ph][c][t] = red[t] + red[t + 64];
    if (t == 0) { g_pm[ph][c] = m; g_ps[ph][c] = s; }
}

__global__ __launch_bounds__(64)
void global_attn_merge_kernel(float* __restrict__ ob) {
    const int ph = blockIdx.x;
    const int h = ph & (NH - 1);
    const int p = (ph >> 4) ? (SEQ - 1) : 0;
    const int t = threadIdx.x;

    float M = -1e30f;
#pragma unroll
    for (int i = 0; i < GCH; i++) M = fmaxf(M, g_pm[ph][i]);
    float S = 0.f, O = 0.f;
#pragma unroll
    for (int i = 0; i < GCH; i++) {
        float w = __expf(g_pm[ph][i] - M);
        S += w * g_ps[ph][i];
        O += w * g_po[ph][i][t];
    }
    ob[(size_t)p * DM + h * HD + t] = O / S;
}

// ---------------------------------------------------------------------------
// Launch
// ---------------------------------------------------------------------------
extern "C" void kernel_launch(void* const* d_in, const int* in_sizes, int n_in,
                              void* d_out, int out_size) {
    const float* Q  = (const float*)d_in[0];
    const float* K  = (const float*)d_in[1];
    const float* V  = (const float*)d_in[2];
    const float* Wq = (const float*)d_in[3];
    const float* Wk = (const float*)d_in[4];
    const float* Wv = (const float*)d_in[5];
    const float* Wo = (const float*)d_in[6];
    const void*  idx = d_in[7];
    float* out = (float*)d_out;

    float *q, *k, *v, *attn;
    cudaGetSymbolAddress((void**)&q,    g_q);
    cudaGetSymbolAddress((void**)&k,    g_k);
    cudaGetSymbolAddress((void**)&v,    g_v);
    cudaGetSymbolAddress((void**)&attn, g_attn);

    detect_idx_kernel<<<1, 1>>>((const int*)idx);

    dim3 gqkv(DM / BN, SEQ / BM, 3);   // (8, 32, 3)
    gemm_tf32_kernel<<<gqkv, 512>>>(Q, Wq, q, K, Wk, k, V, Wv, v);

    dim3 gsp((NNG + TQ - 1) / TQ, NH / 2);   // (512, 8)
    sparse_attn_kernel<<<gsp, 512>>>(q, k, v, idx, attn);

    dim3 gga(GCH, 32);
    global_attn_part_kernel<<<gga, 128>>>(q, k, v);
    global_attn_merge_kernel<<<32, 64>>>(attn);

    dim3 go(DM / BN, SEQ / BM, 1);     // (8, 32)
    gemm_tf32_kernel<<<go, 512>>>(attn, Wo, out, attn, Wo, out, attn, Wo, out);
}

// round 5
// speedup vs baseline: 1.0701x; 1.0379x over previous
#include <cuda_runtime.h>
#include <cstdint>
#include <cstddef>

#define SEQ 4096
#define DM  1024
#define NH  16
#define HD  64
#define NKEY 32
#define NNG 4094

// Scratch (device globals: allocation-free)
__device__ float g_q[SEQ * DM];
__device__ float g_k[SEQ * DM];
__device__ float g_v[SEQ * DM];
__device__ float g_attn[SEQ * DM];
__device__ int   g_idx_is64;

// global-attention split-KV partials
#define GCH 32
__device__ float g_pm[32][GCH];
__device__ float g_ps[32][GCH];
__device__ float g_po[32][GCH][HD];

// ---------------------------------------------------------------------------
__global__ void detect_idx_kernel(const int* __restrict__ idx32) {
    g_idx_is64 = ((idx32[1] | idx32[3] | idx32[5] | idx32[7]) == 0) ? 1 : 0;
}

// ---------------------------------------------------------------------------
// TF32 helpers
// ---------------------------------------------------------------------------
__device__ __forceinline__ uint32_t f2tf32(float x) {
    uint32_t r;
    asm("cvt.rna.tf32.f32 %0, %1;" : "=r"(r) : "f"(x));
    return r;
}

__device__ __forceinline__ void mma_tf32(float c[4], const uint32_t a[4], const uint32_t b[2]) {
    asm volatile(
        "mma.sync.aligned.m16n8k8.row.col.f32.tf32.tf32.f32 "
        "{%0,%1,%2,%3}, {%4,%5,%6,%7}, {%8,%9}, {%0,%1,%2,%3};"
        : "+f"(c[0]), "+f"(c[1]), "+f"(c[2]), "+f"(c[3])
        : "r"(a[0]), "r"(a[1]), "r"(a[2]), "r"(a[3]),
          "r"(b[0]), "r"(b[1]));
}

// ---------------------------------------------------------------------------
// GEMM-A (round-2 proven): 128x128 tile, BK=16, 256 thr = 8 warps (4x2),
// warp tile 32x64. Measured 102.6 us.
// ---------------------------------------------------------------------------
#define BM 128
#define BN 128
#define BK 16
#define PA 20
#define PB 136

__global__ __launch_bounds__(256, 1)
void gemm256_kernel(const float* __restrict__ A, const float* __restrict__ B,
                    float* __restrict__ C) {
    const int N = 1024, K = 1024;
    __shared__ float As[2][BM * PA];
    __shared__ float Bs[2][BK * PB];

    const int bm = blockIdx.y * BM;
    const int bn = blockIdx.x * BN;
    const int t = threadIdx.x;
    const int lane = t & 31;
    const int warp = t >> 5;
    const int wr = warp >> 1;
    const int wc = warp & 1;

    float acc[2][8][4];
#pragma unroll
    for (int mi = 0; mi < 2; mi++)
#pragma unroll
        for (int ni = 0; ni < 8; ni++)
#pragma unroll
            for (int e = 0; e < 4; e++) acc[mi][ni][e] = 0.f;

    {
#pragma unroll
        for (int i = 0; i < 2; i++) {
            int f  = t + i * 256;
            int r  = f >> 2;
            int kc = (f & 3) << 2;
            float4 v4 = *(const float4*)(A + (size_t)(bm + r) * K + kc);
            uint32_t* d = (uint32_t*)&As[0][r * PA + kc];
            d[0] = f2tf32(v4.x); d[1] = f2tf32(v4.y);
            d[2] = f2tf32(v4.z); d[3] = f2tf32(v4.w);

            int kr = f >> 5;
            int cc = (f & 31) << 2;
            float4 w4 = *(const float4*)(B + (size_t)kr * N + bn + cc);
            uint32_t* db = (uint32_t*)&Bs[0][kr * PB + cc];
            db[0] = f2tf32(w4.x); db[1] = f2tf32(w4.y);
            db[2] = f2tf32(w4.z); db[3] = f2tf32(w4.w);
        }
    }
    __syncthreads();

    const int NT = K / BK;
#pragma unroll 1
    for (int kt = 0; kt < NT; kt++) {
        const int cur = kt & 1;

        float4 pa[2], pb[2];
        if (kt < NT - 1) {
            const int k0 = (kt + 1) * BK;
#pragma unroll
            for (int i = 0; i < 2; i++) {
                int f  = t + i * 256;
                int r  = f >> 2;
                int kc = (f & 3) << 2;
                pa[i] = *(const float4*)(A + (size_t)(bm + r) * K + k0 + kc);
                int kr = f >> 5;
                int cc = (f & 31) << 2;
                pb[i] = *(const float4*)(B + (size_t)(k0 + kr) * N + bn + cc);
            }
        }

        const uint32_t* as = (const uint32_t*)&As[cur][0];
        const uint32_t* bs = (const uint32_t*)&Bs[cur][0];
#pragma unroll
        for (int kk = 0; kk < BK; kk += 8) {
            uint32_t af[2][4];
            const int r0 = wr * 32 + (lane >> 2);
            const int ac = kk + (lane & 3);
#pragma unroll
            for (int mi = 0; mi < 2; mi++) {
                int r = r0 + mi * 16;
                af[mi][0] = as[r * PA + ac];
                af[mi][1] = as[(r + 8) * PA + ac];
                af[mi][2] = as[r * PA + ac + 4];
                af[mi][3] = as[(r + 8) * PA + ac + 4];
            }
            uint32_t bf[8][2];
            const int kr = kk + (lane & 3);
            const int c0 = wc * 64 + (lane >> 2);
#pragma unroll
            for (int ni = 0; ni < 8; ni++) {
                int c = c0 + ni * 8;
                bf[ni][0] = bs[kr * PB + c];
                bf[ni][1] = bs[(kr + 4) * PB + c];
            }
#pragma unroll
            for (int mi = 0; mi < 2; mi++)
#pragma unroll
                for (int ni = 0; ni < 8; ni++)
                    mma_tf32(acc[mi][ni], af[mi], bf[ni]);
        }

        if (kt < NT - 1) {
            const int nxt = cur ^ 1;
#pragma unroll
            for (int i = 0; i < 2; i++) {
                int f  = t + i * 256;
                int r  = f >> 2;
                int kc = (f & 3) << 2;
                uint32_t* d = (uint32_t*)&As[nxt][r * PA + kc];
                d[0] = f2tf32(pa[i].x); d[1] = f2tf32(pa[i].y);
                d[2] = f2tf32(pa[i].z); d[3] = f2tf32(pa[i].w);
                int kr = f >> 5;
                int cc = (f & 31) << 2;
                uint32_t* db = (uint32_t*)&Bs[nxt][kr * PB + cc];
                db[0] = f2tf32(pb[i].x); db[1] = f2tf32(pb[i].y);
                db[2] = f2tf32(pb[i].z); db[3] = f2tf32(pb[i].w);
            }
            __syncthreads();
        }
    }

#pragma unroll
    for (int mi = 0; mi < 2; mi++) {
#pragma unroll
        for (int ni = 0; ni < 8; ni++) {
            int r = bm + wr * 32 + mi * 16 + (lane >> 2);
            int c = bn + wc * 64 + ni * 8 + ((lane & 3) << 1);
            float2 v0 = make_float2(acc[mi][ni][0], acc[mi][ni][1]);
            float2 v1 = make_float2(acc[mi][ni][2], acc[mi][ni][3]);
            *(float2*)(C + (size_t)r * N + c) = v0;
            *(float2*)(C + (size_t)(r + 8) * N + c) = v1;
        }
    }
}

// ---------------------------------------------------------------------------
// GEMM-B (A/B experiment, profiled as 4th launch): 128x128 tile, BK=16,
// 512 thr = 16 warps (4x4), warp tile 32x32.
// ---------------------------------------------------------------------------
__global__ __launch_bounds__(512, 1)
void gemm512_kernel(const float* __restrict__ A, const float* __restrict__ B,
                    float* __restrict__ C) {
    const int N = 1024, K = 1024;
    __shared__ float As[2][BM * PA];
    __shared__ float Bs[2][BK * PB];

    const int bm = blockIdx.y * BM;
    const int bn = blockIdx.x * BN;
    const int t = threadIdx.x;
    const int lane = t & 31;
    const int warp = t >> 5;
    const int wr = warp >> 2;
    const int wc = warp & 3;

    const int ar  = t >> 2;
    const int akc = (t & 3) << 2;
    const int bkr = t >> 5;
    const int bcc = (t & 31) << 2;

    float acc[2][4][4];
#pragma unroll
    for (int mi = 0; mi < 2; mi++)
#pragma unroll
        for (int ni = 0; ni < 4; ni++)
#pragma unroll
            for (int e = 0; e < 4; e++) acc[mi][ni][e] = 0.f;

    {
        float4 v4 = *(const float4*)(A + (size_t)(bm + ar) * K + akc);
        uint32_t c4[4] = { f2tf32(v4.x), f2tf32(v4.y), f2tf32(v4.z), f2tf32(v4.w) };
        *(float4*)&As[0][ar * PA + akc] = *(float4*)c4;
        float4 w4 = *(const float4*)(B + (size_t)bkr * N + bn + bcc);
        uint32_t d4[4] = { f2tf32(w4.x), f2tf32(w4.y), f2tf32(w4.z), f2tf32(w4.w) };
        *(float4*)&Bs[0][bkr * PB + bcc] = *(float4*)d4;
    }
    __syncthreads();

    const int NT = K / BK;
#pragma unroll 1
    for (int kt = 0; kt < NT; kt++) {
        const int cur = kt & 1;

        float4 pa, pb;
        if (kt < NT - 1) {
            const int k0 = (kt + 1) * BK;
            pa = *(const float4*)(A + (size_t)(bm + ar) * K + k0 + akc);
            pb = *(const float4*)(B + (size_t)(k0 + bkr) * N + bn + bcc);
        }

        const uint32_t* as = (const uint32_t*)&As[cur][0];
        const uint32_t* bs = (const uint32_t*)&Bs[cur][0];
#pragma unroll
        for (int kk = 0; kk < BK; kk += 8) {
            uint32_t af[2][4];
            const int r0 = wr * 32 + (lane >> 2);
            const int ac = kk + (lane & 3);
#pragma unroll
            for (int mi = 0; mi < 2; mi++) {
                int r = r0 + mi * 16;
                af[mi][0] = as[r * PA + ac];
                af[mi][1] = as[(r + 8) * PA + ac];
                af[mi][2] = as[r * PA + ac + 4];
                af[mi][3] = as[(r + 8) * PA + ac + 4];
            }
            uint32_t bf[4][2];
            const int kr = kk + (lane & 3);
            const int c0 = wc * 32 + (lane >> 2);
#pragma unroll
            for (int ni = 0; ni < 4; ni++) {
                int c = c0 + ni * 8;
                bf[ni][0] = bs[kr * PB + c];
                bf[ni][1] = bs[(kr + 4) * PB + c];
            }
#pragma unroll
            for (int mi = 0; mi < 2; mi++)
#pragma unroll
                for (int ni = 0; ni < 4; ni++)
                    mma_tf32(acc[mi][ni], af[mi], bf[ni]);
        }

        if (kt < NT - 1) {
            const int nxt = cur ^ 1;
            uint32_t c4[4] = { f2tf32(pa.x), f2tf32(pa.y), f2tf32(pa.z), f2tf32(pa.w) };
            *(float4*)&As[nxt][ar * PA + akc] = *(float4*)c4;
            uint32_t d4[4] = { f2tf32(pb.x), f2tf32(pb.y), f2tf32(pb.z), f2tf32(pb.w) };
            *(float4*)&Bs[nxt][bkr * PB + bcc] = *(float4*)d4;
            __syncthreads();
        }
    }

#pragma unroll
    for (int mi = 0; mi < 2; mi++) {
#pragma unroll
        for (int ni = 0; ni < 4; ni++) {
            int r = bm + wr * 32 + mi * 16 + (lane >> 2);
            int c = bn + wc * 32 + ni * 8 + ((lane & 3) << 1);
            float2 v0 = make_float2(acc[mi][ni][0], acc[mi][ni][1]);
            float2 v1 = make_float2(acc[mi][ni][2], acc[mi][ni][3]);
            *(float2*)(C + (size_t)r * N + c) = v0;
            *(float2*)(C + (size_t)(r + 8) * N + c) = v1;
        }
    }
}

// ---------------------------------------------------------------------------
// Sparse attention (round-2 proven): one block per query, 16 warps = 16 heads,
// lane j handles selected key j.
// ---------------------------------------------------------------------------
__global__ __launch_bounds__(512)
void sparse_attn_kernel(const float* __restrict__ qb, const float* __restrict__ kb,
                        const float* __restrict__ vb, const void* __restrict__ idxp,
                        float* __restrict__ ob) {
    __shared__ float qs[DM];
    const int n = blockIdx.x;
    const int p = n + 1;
    const int t = threadIdx.x;

    if (t < DM / 4)
        ((float4*)qs)[t] = ((const float4*)(qb + (size_t)p * DM))[t];
    __syncthreads();

    const int h = t >> 5;
    const int lane = t & 31;

    int row;
    if (g_idx_is64) {
        row = (int)((const long long*)idxp)[(size_t)n * NKEY + lane];
    } else {
        row = ((const int*)idxp)[(size_t)n * NKEY + lane];
    }

    const float* kr = kb + (size_t)row * DM + h * HD;
    const float* qh = qs + h * HD;

    float a = 0.f;
#pragma unroll
    for (int c = 0; c < 16; c++) {
        float4 kv = ((const float4*)kr)[c];
        float4 qv = ((const float4*)qh)[c];
        a += kv.x * qv.x + kv.y * qv.y + kv.z * qv.z + kv.w * qv.w;
    }
    float logit = a * 0.125f;

    float m = logit;
#pragma unroll
    for (int o = 16; o > 0; o >>= 1) m = fmaxf(m, __shfl_xor_sync(0xFFFFFFFFu, m, o));
    float e = __expf(logit - m);
    float s = e;
#pragma unroll
    for (int o = 16; o > 0; o >>= 1) s += __shfl_xor_sync(0xFFFFFFFFu, s, o);
    const float prob = e / s;

    float o0 = 0.f, o1 = 0.f;
#pragma unroll
    for (int j = 0; j < NKEY; j++) {
        float pj = __shfl_sync(0xFFFFFFFFu, prob, j);
        int   rj = __shfl_sync(0xFFFFFFFFu, row, j);
        const float* vr = vb + (size_t)rj * DM + h * HD;
        o0 += pj * vr[lane];
        o1 += pj * vr[32 + lane];
    }
    ob[(size_t)p * DM + h * HD + lane] = o0;
    ob[(size_t)p * DM + h * HD + 32 + lane] = o1;
}

// ---------------------------------------------------------------------------
// Global attention, split-KV (round-4 proven: 22+2 us).
// ---------------------------------------------------------------------------
__global__ __launch_bounds__(128)
void global_attn_part_kernel(const float* __restrict__ qb, const float* __restrict__ kb,
                             const float* __restrict__ vb) {
    __shared__ float qsh[HD];
    __shared__ float le[128];
    __shared__ float red[128];

    const int c = blockIdx.x;
    const int ph = blockIdx.y;
    const int h = ph & (NH - 1);
    const int p = (ph >> 4) ? (SEQ - 1) : 0;
    const int t = threadIdx.x;
    const int j0 = c * 128;

    if (t < HD / 4)
        ((float4*)qsh)[t] = *(const float4*)(qb + (size_t)p * DM + h * HD + t * 4);
    __syncthreads();

    const float* kr = kb + (size_t)(j0 + t) * DM + h * HD;
    float a = 0.f;
#pragma unroll
    for (int cc = 0; cc < 16; cc++) {
        float4 kv = ((const float4*)kr)[cc];
        float4 qv = ((const float4*)qsh)[cc];
        a += kv.x * qv.x + kv.y * qv.y + kv.z * qv.z + kv.w * qv.w;
    }
    float logit = a * 0.125f;

    red[t] = logit; __syncthreads();
#pragma unroll
    for (int o = 64; o > 0; o >>= 1) {
        if (t < o) red[t] = fmaxf(red[t], red[t + o]);
        __syncthreads();
    }
    const float m = red[0];
    __syncthreads();

    float e = __expf(logit - m);
    le[t] = e;
    red[t] = e; __syncthreads();
#pragma unroll
    for (int o = 64; o > 0; o >>= 1) {
        if (t < o) red[t] += red[t + o];
        __syncthreads();
    }
    const float s = red[0];
    __syncthreads();

    const int d = t & (HD - 1);
    const int half = t >> 6;
    float o = 0.f;
#pragma unroll 4
    for (int j = half * 64; j < half * 64 + 64; j++)
        o += le[j] * vb[(size_t)(j0 + j) * DM + h * HD + d];
    red[t] = o; __syncthreads();
    if (t < HD)
        g_po[ph][c][t] = red[t] + red[t + 64];
    if (t == 0) { g_pm[ph][c] = m; g_ps[ph][c] = s; }
}

__global__ __launch_bounds__(64)
void global_attn_merge_kernel(float* __restrict__ ob) {
    const int ph = blockIdx.x;
    const int h = ph & (NH - 1);
    const int p = (ph >> 4) ? (SEQ - 1) : 0;
    const int t = threadIdx.x;

    float M = -1e30f;
#pragma unroll
    for (int i = 0; i < GCH; i++) M = fmaxf(M, g_pm[ph][i]);
    float S = 0.f, O = 0.f;
#pragma unroll
    for (int i = 0; i < GCH; i++) {
        float w = __expf(g_pm[ph][i] - M);
        S += w * g_ps[ph][i];
        O += w * g_po[ph][i][t];
    }
    ob[(size_t)p * DM + h * HD + t] = O / S;
}

// ---------------------------------------------------------------------------
// Launch. NOTE: ncu captures the 4th launch -> gemm512 (V projection) is
// deliberately placed 4th for the A/B experiment.
// ---------------------------------------------------------------------------
extern "C" void kernel_launch(void* const* d_in, const int* in_sizes, int n_in,
                              void* d_out, int out_size) {
    const float* Q  = (const float*)d_in[0];
    const float* K  = (const float*)d_in[1];
    const float* V  = (const float*)d_in[2];
    const float* Wq = (const float*)d_in[3];
    const float* Wk = (const float*)d_in[4];
    const float* Wv = (const float*)d_in[5];
    const float* Wo = (const float*)d_in[6];
    const void*  idx = d_in[7];
    float* out = (float*)d_out;

    float *q, *k, *v, *attn;
    cudaGetSymbolAddress((void**)&q,    g_q);
    cudaGetSymbolAddress((void**)&k,    g_k);
    cudaGetSymbolAddress((void**)&v,    g_v);
    cudaGetSymbolAddress((void**)&attn, g_attn);

    detect_idx_kernel<<<1, 1>>>((const int*)idx);           // launch 1

    dim3 gg(DM / BN, SEQ / BM);                              // (8, 32)
    gemm256_kernel<<<gg, 256>>>(Q, Wq, q);                   // launch 2
    gemm256_kernel<<<gg, 256>>>(K, Wk, k);                   // launch 3
    gemm512_kernel<<<gg, 512>>>(V, Wv, v);                   // launch 4 (profiled)

    sparse_attn_kernel<<<NNG, 512>>>(q, k, v, idx, attn);    // launch 5

    dim3 gga(GCH, 32);
    global_attn_part_kernel<<<gga, 128>>>(q, k, v);          // launch 6
    global_attn_merge_kernel<<<32, 64>>>(attn);              // launch 7

    gemm256_kernel<<<gg, 256>>>(attn, Wo, out);              // launch 8
}

// round 7
// speedup vs baseline: 1.3268x; 1.2398x over previous
#include <cuda_runtime.h>
#include <cstdint>
#include <cstddef>

#define SEQ 4096
#define DM  1024
#define NH  16
#define HD  64
#define NKEY 32
#define NNG 4094

// Scratch (device globals: allocation-free)
__device__ float g_q[SEQ * DM];
__device__ float g_k[SEQ * DM];
__device__ float g_v[SEQ * DM];
__device__ float g_attn[SEQ * DM];
__device__ int   g_idx_is64;

#define GCH 32
__device__ float g_pm[32][GCH];
__device__ float g_ps[32][GCH];
__device__ float g_po[32][GCH][HD];

// ---------------------------------------------------------------------------
__global__ void detect_idx_kernel(const int* __restrict__ idx32) {
    g_idx_is64 = ((idx32[1] | idx32[3] | idx32[5] | idx32[7]) == 0) ? 1 : 0;
}

// ---------------------------------------------------------------------------
// TF32 helpers
// ---------------------------------------------------------------------------
__device__ __forceinline__ uint32_t f2tf32(float x) {
    uint32_t r;
    asm("cvt.rna.tf32.f32 %0, %1;" : "=r"(r) : "f"(x));
    return r;
}
__device__ __forceinline__ float rndf(float x) { return __uint_as_float(f2tf32(x)); }

__device__ __forceinline__ void mma_tf32(float c[4], const uint32_t a[4], const uint32_t b[2]) {
    asm volatile(
        "mma.sync.aligned.m16n8k8.row.col.f32.tf32.tf32.f32 "
        "{%0,%1,%2,%3}, {%4,%5,%6,%7}, {%8,%9}, {%0,%1,%2,%3};"
        : "+f"(c[0]), "+f"(c[1]), "+f"(c[2]), "+f"(c[3])
        : "r"(a[0]), "r"(a[1]), "r"(a[2]), "r"(a[3]),
          "r"(b[0]), "r"(b[1]));
}

// ---------------------------------------------------------------------------
// GEMM v4: C[4096,1024] = A[4096,1024] * B[1024,1024], fp32 in/out, tf32 MMA.
// 128x128 block tile, BK=16, 256 thr = 8 warps (2 M x 4 N), warp tile 64x32.
// A smem: [row][16] with XOR-permuted k layout -> LDS.128 loads a thread's
// A-fragment for BOTH k-steps; conflict-free loads AND stores.
// B smem: [k][136] row-major (round-2 proven layout), LDS.32 fragments.
// Double-buffered; 2 CTAs/SM.
// ---------------------------------------------------------------------------
#define BK 16
#define PBf 136

__global__ void __launch_bounds__(256, 2)
gemm_fast_kernel(const float* __restrict__ A, const float* __restrict__ B,
                 float* __restrict__ C) {
    const int N = 1024, K = 1024;
    __shared__ float As[2][128 * 16];    // 16 KB
    __shared__ float Bs[2][BK * PBf];    // 17.4 KB

    const int t = threadIdx.x;
    const int lane = t & 31;
    const int warp = t >> 5;
    const int wr = warp >> 2;    // 0..1 (64-row slabs)
    const int wc = warp & 3;     // 0..3 (32-col slabs)
    const int bm = blockIdx.y * 128;
    const int bn = blockIdx.x * 128;

    float acc[4][4][4];
#pragma unroll
    for (int mi = 0; mi < 4; mi++)
#pragma unroll
        for (int ni = 0; ni < 4; ni++)
#pragma unroll
            for (int e = 0; e < 4; e++) acc[mi][ni][e] = 0.f;

    // ---- staging helper indices ----
    // A: f = t + 256*i -> row = f>>2 (0..127), kc4 = f&3 (k-offset kc4*4)
    // B: f = t + 256*i -> krow = f>>5 (0..15), nc = (f&31)*4

    // ---- prologue: tile 0 -> buffer 0 ----
#pragma unroll
    for (int i = 0; i < 2; i++) {
        const int f = t + (i << 8);
        const int row = f >> 2, kc4 = f & 3;
        float4 va = *(const float4*)(A + (size_t)(bm + row) * K + kc4 * 4);
        const int xa = (row >> 1) & 3;
        float* ab = &As[0][row * 16 + kc4];
        ab[((0 ^ xa) & 3) * 4] = rndf(va.x);
        ab[((1 ^ xa) & 3) * 4] = rndf(va.y);
        ab[((2 ^ xa) & 3) * 4] = rndf(va.z);
        ab[((3 ^ xa) & 3) * 4] = rndf(va.w);

        const int krow = f >> 5, nc = (f & 31) << 2;
        float4 vb = *(const float4*)(B + (size_t)krow * N + bn + nc);
        uint32_t d4[4] = { f2tf32(vb.x), f2tf32(vb.y), f2tf32(vb.z), f2tf32(vb.w) };
        *(float4*)&Bs[0][krow * PBf + nc] = *(float4*)d4;
    }
    __syncthreads();

    const int NT = K / BK;   // 64
#pragma unroll 1
    for (int kt = 0; kt < NT; kt++) {
        const int cur = kt & 1;

        // ---- prefetch next tile (global -> regs) ----
        float4 pa[2], pb[2];
        if (kt < NT - 1) {
            const int k0 = (kt + 1) * BK;
#pragma unroll
            for (int i = 0; i < 2; i++) {
                const int f = t + (i << 8);
                pa[i] = *(const float4*)(A + (size_t)(bm + (f >> 2)) * K + k0 + (f & 3) * 4);
                pb[i] = *(const float4*)(B + (size_t)(k0 + (f >> 5)) * N + bn + ((f & 31) << 2));
            }
        }

        // ---- compute on current buffer ----
        const float4* as4 = (const float4*)&As[cur][0];
        const float*  bsc = &Bs[cur][0];

        // preload all B fragments (covers both k-steps)
        uint32_t bfr[4][4];
        {
            const int kr = lane & 3;
            const int c0 = wc * 32 + (lane >> 2);
#pragma unroll
            for (int ni = 0; ni < 4; ni++) {
                const int c = c0 + ni * 8;
                bfr[ni][0] = __float_as_uint(bsc[kr * PBf + c]);
                bfr[ni][1] = __float_as_uint(bsc[(kr + 4) * PBf + c]);
                bfr[ni][2] = __float_as_uint(bsc[(kr + 8) * PBf + c]);
                bfr[ni][3] = __float_as_uint(bsc[(kr + 12) * PBf + c]);
            }
        }
#pragma unroll
        for (int mi = 0; mi < 4; mi++) {
            const int rlo = wr * 64 + mi * 16 + (lane >> 2);
            const int rhi = rlo + 8;
            float4 alo = as4[rlo * 4 + (((lane & 3) ^ (rlo >> 1)) & 3)];
            float4 ahi = as4[rhi * 4 + (((lane & 3) ^ (rhi >> 1)) & 3)];
            uint32_t a0[4] = { __float_as_uint(alo.x), __float_as_uint(ahi.x),
                               __float_as_uint(alo.y), __float_as_uint(ahi.y) };
            uint32_t a1[4] = { __float_as_uint(alo.z), __float_as_uint(ahi.z),
                               __float_as_uint(alo.w), __float_as_uint(ahi.w) };
#pragma unroll
            for (int ni = 0; ni < 4; ni++) {
                mma_tf32(acc[mi][ni], a0, &bfr[ni][0]);
                mma_tf32(acc[mi][ni], a1, &bfr[ni][2]);
            }
        }

        // ---- store prefetched tile into other buffer ----
        if (kt < NT - 1) {
            const int nxt = cur ^ 1;
#pragma unroll
            for (int i = 0; i < 2; i++) {
                const int f = t + (i << 8);
                const int row = f >> 2, kc4 = f & 3;
                const int xa = (row >> 1) & 3;
                float* ab = &As[nxt][row * 16 + kc4];
                ab[((0 ^ xa) & 3) * 4] = rndf(pa[i].x);
                ab[((1 ^ xa) & 3) * 4] = rndf(pa[i].y);
                ab[((2 ^ xa) & 3) * 4] = rndf(pa[i].z);
                ab[((3 ^ xa) & 3) * 4] = rndf(pa[i].w);

                const int krow = f >> 5, nc = (f & 31) << 2;
                uint32_t d4[4] = { f2tf32(pb[i].x), f2tf32(pb[i].y),
                                   f2tf32(pb[i].z), f2tf32(pb[i].w) };
                *(float4*)&Bs[nxt][krow * PBf + nc] = *(float4*)d4;
            }
            __syncthreads();
        }
    }

    // ---- epilogue ----
#pragma unroll
    for (int mi = 0; mi < 4; mi++) {
#pragma unroll
        for (int ni = 0; ni < 4; ni++) {
            const int r = bm + wr * 64 + mi * 16 + (lane >> 2);
            const int c = bn + wc * 32 + ni * 8 + ((lane & 3) << 1);
            float2 v0 = make_float2(acc[mi][ni][0], acc[mi][ni][1]);
            float2 v1 = make_float2(acc[mi][ni][2], acc[mi][ni][3]);
            *(float2*)(C + (size_t)r * N + c) = v0;
            *(float2*)(C + (size_t)(r + 8) * N + c) = v1;
        }
    }
}

// ---------------------------------------------------------------------------
// Sparse attention (proven): one block per query, 16 warps = 16 heads,
// lane j handles selected key j.
// ---------------------------------------------------------------------------
__global__ __launch_bounds__(512)
void sparse_attn_kernel(const float* __restrict__ qb, const float* __restrict__ kb,
                        const float* __restrict__ vb, const void* __restrict__ idxp,
                        float* __restrict__ ob) {
    __shared__ float qs[DM];
    const int n = blockIdx.x;
    const int p = n + 1;
    const int t = threadIdx.x;

    if (t < DM / 4)
        ((float4*)qs)[t] = ((const float4*)(qb + (size_t)p * DM))[t];
    __syncthreads();

    const int h = t >> 5;
    const int lane = t & 31;

    int row;
    if (g_idx_is64) {
        row = (int)((const long long*)idxp)[(size_t)n * NKEY + lane];
    } else {
        row = ((const int*)idxp)[(size_t)n * NKEY + lane];
    }

    const float* kr = kb + (size_t)row * DM + h * HD;
    const float* qh = qs + h * HD;

    float a = 0.f;
#pragma unroll
    for (int c = 0; c < 16; c++) {
        float4 kv = ((const float4*)kr)[c];
        float4 qv = ((const float4*)qh)[c];
        a += kv.x * qv.x + kv.y * qv.y + kv.z * qv.z + kv.w * qv.w;
    }
    float logit = a * 0.125f;

    float m = logit;
#pragma unroll
    for (int o = 16; o > 0; o >>= 1) m = fmaxf(m, __shfl_xor_sync(0xFFFFFFFFu, m, o));
    float e = __expf(logit - m);
    float s = e;
#pragma unroll
    for (int o = 16; o > 0; o >>= 1) s += __shfl_xor_sync(0xFFFFFFFFu, s, o);
    const float prob = e / s;

    float o0 = 0.f, o1 = 0.f;
#pragma unroll
    for (int j = 0; j < NKEY; j++) {
        float pj = __shfl_sync(0xFFFFFFFFu, prob, j);
        int   rj = __shfl_sync(0xFFFFFFFFu, row, j);
        const float* vr = vb + (size_t)rj * DM + h * HD;
        o0 += pj * vr[lane];
        o1 += pj * vr[32 + lane];
    }
    ob[(size_t)p * DM + h * HD + lane] = o0;
    ob[(size_t)p * DM + h * HD + 32 + lane] = o1;
}

// ---------------------------------------------------------------------------
// Global attention, split-KV (proven: ~24 us total).
// ---------------------------------------------------------------------------
__global__ __launch_bounds__(128)
void global_attn_part_kernel(const float* __restrict__ qb, const float* __restrict__ kb,
                             const float* __restrict__ vb) {
    __shared__ float qsh[HD];
    __shared__ float le[128];
    __shared__ float red[128];

    const int c = blockIdx.x;
    const int ph = blockIdx.y;
    const int h = ph & (NH - 1);
    const int p = (ph >> 4) ? (SEQ - 1) : 0;
    const int t = threadIdx.x;
    const int j0 = c * 128;

    if (t < HD / 4)
        ((float4*)qsh)[t] = *(const float4*)(qb + (size_t)p * DM + h * HD + t * 4);
    __syncthreads();

    const float* kr = kb + (size_t)(j0 + t) * DM + h * HD;
    float a = 0.f;
#pragma unroll
    for (int cc = 0; cc < 16; cc++) {
        float4 kv = ((const float4*)kr)[cc];
        float4 qv = ((const float4*)qsh)[cc];
        a += kv.x * qv.x + kv.y * qv.y + kv.z * qv.z + kv.w * qv.w;
    }
    float logit = a * 0.125f;

    red[t] = logit; __syncthreads();
#pragma unroll
    for (int o = 64; o > 0; o >>= 1) {
        if (t < o) red[t] = fmaxf(red[t], red[t + o]);
        __syncthreads();
    }
    const float m = red[0];
    __syncthreads();

    float e = __expf(logit - m);
    le[t] = e;
    red[t] = e; __syncthreads();
#pragma unroll
    for (int o = 64; o > 0; o >>= 1) {
        if (t < o) red[t] += red[t + o];
        __syncthreads();
    }
    const float s = red[0];
    __syncthreads();

    const int d = t & (HD - 1);
    const int half = t >> 6;
    float o = 0.f;
#pragma unroll 4
    for (int j = half * 64; j < half * 64 + 64; j++)
        o += le[j] * vb[(size_t)(j0 + j) * DM + h * HD + d];
    red[t] = o; __syncthreads();
    if (t < HD)
        g_po[ph][c][t] = red[t] + red[t + 64];
    if (t == 0) { g_pm[ph][c] = m; g_ps[ph][c] = s; }
}

__global__ __launch_bounds__(64)
void global_attn_merge_kernel(float* __restrict__ ob) {
    const int ph = blockIdx.x;
    const int h = ph & (NH - 1);
    const int p = (ph >> 4) ? (SEQ - 1) : 0;
    const int t = threadIdx.x;

    float M = -1e30f;
#pragma unroll
    for (int i = 0; i < GCH; i++) M = fmaxf(M, g_pm[ph][i]);
    float S = 0.f, O = 0.f;
#pragma unroll
    for (int i = 0; i < GCH; i++) {
        float w = __expf(g_pm[ph][i] - M);
        S += w * g_ps[ph][i];
        O += w * g_po[ph][i][t];
    }
    ob[(size_t)p * DM + h * HD + t] = O / S;
}

// ---------------------------------------------------------------------------
// Launch. ncu profiles the 4th launch -> gemm_fast (V projection).
// ---------------------------------------------------------------------------
extern "C" void kernel_launch(void* const* d_in, const int* in_sizes, int n_in,
                              void* d_out, int out_size) {
    const float* Q  = (const float*)d_in[0];
    const float* K  = (const float*)d_in[1];
    const float* V  = (const float*)d_in[2];
    const float* Wq = (const float*)d_in[3];
    const float* Wk = (const float*)d_in[4];
    const float* Wv = (const float*)d_in[5];
    const float* Wo = (const float*)d_in[6];
    const void*  idx = d_in[7];
    float* out = (float*)d_out;

    float *q, *k, *v, *attn;
    cudaGetSymbolAddress((void**)&q,    g_q);
    cudaGetSymbolAddress((void**)&k,    g_k);
    cudaGetSymbolAddress((void**)&v,    g_v);
    cudaGetSymbolAddress((void**)&attn, g_attn);

    detect_idx_kernel<<<1, 1>>>((const int*)idx);            // 1

    dim3 gg(8, 32);                                          // 256 blocks
    gemm_fast_kernel<<<gg, 256>>>(Q, Wq, q);                 // 2
    gemm_fast_kernel<<<gg, 256>>>(K, Wk, k);                 // 3
    gemm_fast_kernel<<<gg, 256>>>(V, Wv, v);                 // 4 (profiled)

    sparse_attn_kernel<<<NNG, 512>>>(q, k, v, idx, attn);    // 5

    dim3 gga(GCH, 32);
    global_attn_part_kernel<<<gga, 128>>>(q, k, v);          // 6
    global_attn_merge_kernel<<<32, 64>>>(attn);              // 7

    gemm_fast_kernel<<<gg, 256>>>(attn, Wo, out);            // 8
}

// round 8
// speedup vs baseline: 1.3911x; 1.0485x over previous
#include <cuda_runtime.h>
#include <cstdint>
#include <cstddef>

#define SEQ 4096
#define DM  1024
#define NH  16
#define HD  64
#define NKEY 32
#define NNG 4094

// Scratch (device globals: allocation-free)
__device__ float g_q[SEQ * DM];
__device__ float g_k[SEQ * DM];
__device__ float g_v[SEQ * DM];
__device__ float g_attn[SEQ * DM];
__device__ float g_qp[SEQ * DM];      // permuted+rounded A operands
__device__ float g_kp[SEQ * DM];
__device__ float g_vp[SEQ * DM];
__device__ float g_attnp[SEQ * DM];
__device__ float g_wqp[DM * DM];      // permuted+rounded weights [kt][n][16]
__device__ float g_wkp[DM * DM];
__device__ float g_wvp[DM * DM];
__device__ float g_wop[DM * DM];
__device__ int   g_idx_is64;

#define GCH 32
__device__ float g_pm[32][GCH];
__device__ float g_ps[32][GCH];
__device__ float g_po[32][GCH][HD];

// ---------------------------------------------------------------------------
__global__ void detect_idx_kernel(const int* __restrict__ idx32) {
    g_idx_is64 = ((idx32[1] | idx32[3] | idx32[5] | idx32[7]) == 0) ? 1 : 0;
}

// ---------------------------------------------------------------------------
// Helpers
// ---------------------------------------------------------------------------
__device__ __forceinline__ uint32_t f2tf32(float x) {
    uint32_t r;
    asm("cvt.rna.tf32.f32 %0, %1;" : "=r"(r) : "f"(x));
    return r;
}
__device__ __forceinline__ float rndf(float x) { return __uint_as_float(f2tf32(x)); }

__device__ __forceinline__ uint32_t smem_u32(const void* p) {
    uint32_t a;
    asm("{ .reg .u64 t; cvta.to.shared.u64 t, %1; cvt.u32.u64 %0, t; }" : "=r"(a) : "l"(p));
    return a;
}
__device__ __forceinline__ void cp16(uint32_t dst, const void* src) {
    asm volatile("cp.async.cg.shared.global [%0], [%1], 16;" :: "r"(dst), "l"(src));
}
__device__ __forceinline__ void mma_tf32(float c[4], const uint32_t a[4], const uint32_t b[2]) {
    asm volatile(
        "mma.sync.aligned.m16n8k8.row.col.f32.tf32.tf32.f32 "
        "{%0,%1,%2,%3}, {%4,%5,%6,%7}, {%8,%9}, {%0,%1,%2,%3};"
        : "+f"(c[0]), "+f"(c[1]), "+f"(c[2]), "+f"(c[3])
        : "r"(a[0]), "r"(a[1]), "r"(a[2]), "r"(a[3]),
          "r"(b[0]), "r"(b[1]));
}

// ---------------------------------------------------------------------------
// A-operand permute+round: per row, per 16-k chunk, value k goes to position
// ((k%4)^xa)*4 + k/4, xa = (row>>1)&3. Output quad x = {in[(x^xa)+4u]}.
// z selects one of up to 3 (src,dst) pairs.
// ---------------------------------------------------------------------------
__global__ __launch_bounds__(256)
void perm_a_kernel(const float* __restrict__ s0, float* __restrict__ d0,
                   const float* __restrict__ s1, float* __restrict__ d1,
                   const float* __restrict__ s2, float* __restrict__ d2) {
    const float* src = (blockIdx.z == 0) ? s0 : (blockIdx.z == 1) ? s1 : s2;
    float*       dst = (blockIdx.z == 0) ? d0 : (blockIdx.z == 1) ? d1 : d2;
    const int idx = blockIdx.x * 256 + threadIdx.x;   // chunk id 0..262143
    const int row = idx >> 6, ch = idx & 63;
    const float4* s = (const float4*)(src + (size_t)row * DM + ch * 16);
    float4 u0 = s[0], u1 = s[1], u2 = s[2], u3 = s[3];
    float vv[16] = { u0.x,u0.y,u0.z,u0.w, u1.x,u1.y,u1.z,u1.w,
                     u2.x,u2.y,u2.z,u2.w, u3.x,u3.y,u3.z,u3.w };
    const int xa = (row >> 1) & 3;
    float4* d = (float4*)(dst + (size_t)row * DM + ch * 16);
#pragma unroll
    for (int x = 0; x < 4; x++) {
        const int kq = x ^ xa;
        float4 o;
        o.x = rndf(vv[kq]); o.y = rndf(vv[kq + 4]);
        o.z = rndf(vv[kq + 8]); o.w = rndf(vv[kq + 12]);
        d[x] = o;
    }
}

// ---------------------------------------------------------------------------
// Weight permute+round: Wp[kt][n][inner] = rnd(W[kt*16+k][n]),
// inner = (k&3)*4 + (k>>2). z selects one of 4 weights.
// ---------------------------------------------------------------------------
__global__ __launch_bounds__(256)
void perm_w_kernel(const float* __restrict__ W0, float* __restrict__ P0,
                   const float* __restrict__ W1, float* __restrict__ P1,
                   const float* __restrict__ W2, float* __restrict__ P2,
                   const float* __restrict__ W3, float* __restrict__ P3) {
    const float* W = (blockIdx.z == 0) ? W0 : (blockIdx.z == 1) ? W1 : (blockIdx.z == 2) ? W2 : W3;
    float*       P = (blockIdx.z == 0) ? P0 : (blockIdx.z == 1) ? P1 : (blockIdx.z == 2) ? P2 : P3;
    const int idx = blockIdx.x * 256 + threadIdx.x;   // 0..65535
    const int kt = idx >> 10, n = idx & 1023;
    float out[16];
#pragma unroll
    for (int k = 0; k < 16; k++)
        out[((k & 3) << 2) + (k >> 2)] = rndf(W[(size_t)(kt * 16 + k) * DM + n]);
    float4* d = (float4*)(P + (size_t)kt * (DM * 16) + (size_t)n * 16);
#pragma unroll
    for (int x = 0; x < 4; x++)
        d[x] = make_float4(out[4 * x], out[4 * x + 1], out[4 * x + 2], out[4 * x + 3]);
}

// ---------------------------------------------------------------------------
// GEMM v5: C[4096,1024] = Ap * Wp^T. 128x128 tile, BK=16, 256 thr = 8 warps
// (2M x 4N), warp tile 64x32. Pre-permuted operands -> staging is contiguous
// cp.async; A frags 8 LDS.128, B frags 4 LDS.128. 3-stage pipeline, 2 CTA/SM.
// ---------------------------------------------------------------------------
#define STG 16384           // bytes per stage: 8KB A + 8KB B
#define GEMM_SMEM (3 * STG)

__device__ __forceinline__ void gemm_issue(uint32_t sb, int s, int t,
                                           const float* Arow, const float* Bkt) {
    const uint32_t ab = sb + s * STG;
    const uint32_t bb = ab + 8192;
#pragma unroll
    for (int i = 0; i < 2; i++) {
        const int ch = t + (i << 8);
        cp16(ab + ch * 16, Arow + (size_t)(ch >> 2) * DM + (ch & 3) * 4);
        cp16(bb + ch * 16, Bkt + ch * 4);
    }
    asm volatile("cp.async.commit_group;" ::: "memory");
}

__global__ void __launch_bounds__(256, 2)
gemm_v5_kernel(const float* __restrict__ Ap, const float* __restrict__ Wp,
               float* __restrict__ C) {
    extern __shared__ char sm[];
    const uint32_t sb = smem_u32(sm);
    const int t = threadIdx.x, lane = t & 31, warp = t >> 5;
    const int wr = warp >> 2, wc = warp & 3;
    const int bm = blockIdx.y * 128, bn = blockIdx.x * 128;

    const float* Abase = Ap + (size_t)bm * DM;         // + kt*16 per tile
    const float* Bbase = Wp + (size_t)bn * 16;         // + kt*16384 per tile

    float acc[4][4][4];
#pragma unroll
    for (int mi = 0; mi < 4; mi++)
#pragma unroll
        for (int ni = 0; ni < 4; ni++)
#pragma unroll
            for (int e = 0; e < 4; e++) acc[mi][ni][e] = 0.f;

    gemm_issue(sb, 0, t, Abase, Bbase);
    gemm_issue(sb, 1, t, Abase + 16, Bbase + (size_t)DM * 16);

    const int NT = 64;
#pragma unroll 1
    for (int kt = 0; kt < NT; kt++) {
        const int s = kt - (kt / 3) * 3;
        if (kt < NT - 1) asm volatile("cp.async.wait_group 1;" ::: "memory");
        else             asm volatile("cp.async.wait_group 0;" ::: "memory");
        __syncthreads();

        const float4* as4 = (const float4*)(sm + s * STG);
        const float4* bs4 = (const float4*)(sm + s * STG + 8192);

        // B fragments: one LDS.128 per ni covers both k-steps
        float4 bq[4];
        {
            const int c0 = wc * 32 + (lane >> 2);
            const int g = lane & 3;
#pragma unroll
            for (int ni = 0; ni < 4; ni++)
                bq[ni] = bs4[(c0 + ni * 8) * 4 + g];
        }
#pragma unroll
        for (int mi = 0; mi < 4; mi++) {
            const int rlo = wr * 64 + mi * 16 + (lane >> 2);
            const int rhi = rlo + 8;
            float4 alo = as4[rlo * 4 + (((lane & 3) ^ (rlo >> 1)) & 3)];
            float4 ahi = as4[rhi * 4 + (((lane & 3) ^ (rhi >> 1)) & 3)];
            uint32_t a0[4] = { __float_as_uint(alo.x), __float_as_uint(ahi.x),
                               __float_as_uint(alo.y), __float_as_uint(ahi.y) };
            uint32_t a1[4] = { __float_as_uint(alo.z), __float_as_uint(ahi.z),
                               __float_as_uint(alo.w), __float_as_uint(ahi.w) };
#pragma unroll
            for (int ni = 0; ni < 4; ni++) {
                uint32_t b0[2] = { __float_as_uint(bq[ni].x), __float_as_uint(bq[ni].y) };
                uint32_t b1[2] = { __float_as_uint(bq[ni].z), __float_as_uint(bq[ni].w) };
                mma_tf32(acc[mi][ni], a0, b0);
                mma_tf32(acc[mi][ni], a1, b1);
            }
        }

        if (kt + 2 < NT) {
            const int ns = (kt + 2) - ((kt + 2) / 3) * 3;
            gemm_issue(sb, ns, t, Abase + (kt + 2) * 16, Bbase + (size_t)(kt + 2) * DM * 16);
        }
    }

    // epilogue
#pragma unroll
    for (int mi = 0; mi < 4; mi++) {
#pragma unroll
        for (int ni = 0; ni < 4; ni++) {
            const int r = bm + wr * 64 + mi * 16 + (lane >> 2);
            const int c = bn + wc * 32 + ni * 8 + ((lane & 3) << 1);
            float2 v0 = make_float2(acc[mi][ni][0], acc[mi][ni][1]);
            float2 v1 = make_float2(acc[mi][ni][2], acc[mi][ni][3]);
            *(float2*)(C + (size_t)r * DM + c) = v0;
            *(float2*)(C + (size_t)(r + 8) * DM + c) = v1;
        }
    }
}

// ---------------------------------------------------------------------------
// Sparse attention v2 (round-3, passed; window keys staged in smem).
// Block = 8 adjacent queries x 2 heads (16 warps).
// ---------------------------------------------------------------------------
#define TQ 8
#define WROWS 30

__global__ __launch_bounds__(512)
void sparse_attn_kernel(const float* __restrict__ qb, const float* __restrict__ kb,
                        const float* __restrict__ vb, const void* __restrict__ idxp,
                        float* __restrict__ ob) {
    __shared__ float sQ[TQ][128];
    __shared__ float sK[WROWS][128];
    __shared__ float sV[WROWS][128];

    const int t = threadIdx.x;
    const int pbase = blockIdx.x * TQ + 1;
    const int hb = blockIdx.y * 128;
    const int r0 = pbase - 11;

    if (t < 256) {
        int row = t >> 5, i = (t & 31) << 2;
        int p = pbase + row;
        if (p <= SEQ - 2)
            *(float4*)&sQ[row][i] = *(const float4*)(qb + (size_t)p * DM + hb + i);
    }
#pragma unroll
    for (int f = 0; f < 2 * WROWS * 32; f += 512) {
        int g = f + t;
        if (g < 2 * WROWS * 32) {
            int sel = (g >= WROWS * 32);
            int rem = sel ? g - WROWS * 32 : g;
            int row = rem >> 5, i = (rem & 31) << 2;
            int rg = r0 + row;
            rg = rg < 0 ? 0 : (rg > SEQ - 1 ? SEQ - 1 : rg);
            const float* src = (sel ? vb : kb) + (size_t)rg * DM + hb + i;
            float* dst = (sel ? &sV[0][0] : &sK[0][0]) + row * 128 + i;
            *(float4*)dst = *(const float4*)src;
        }
    }
    __syncthreads();

    const int warp = t >> 5, lane = t & 31;
    const int ql = warp & 7, hl = warp >> 3;
    const int p = pbase + ql;
    if (p > SEQ - 2) return;
    const int n = p - 1;
    const int hdim = hb + hl * 64;

    const float* kp;
    const float* vp;
    if (lane >= 9) {
        int rl = ql + lane - 9;
        kp = &sK[rl][hl * 64];
        vp = &sV[rl][hl * 64];
    } else {
        int row = 0;
        if (lane >= 1) {
            row = g_idx_is64
                ? (int)((const long long*)idxp)[(size_t)n * NKEY + lane]
                : ((const int*)idxp)[(size_t)n * NKEY + lane];
        }
        kp = kb + (size_t)row * DM + hdim;
        vp = vb + (size_t)row * DM + hdim;
    }
    const float* qp = &sQ[ql][hl * 64];

    float a = 0.f;
#pragma unroll
    for (int c = 0; c < 16; c++) {
        float4 kv = ((const float4*)kp)[c];
        float4 qv = ((const float4*)qp)[c];
        a += kv.x * qv.x + kv.y * qv.y + kv.z * qv.z + kv.w * qv.w;
    }
    float logit = a * 0.125f;

    float m = logit;
#pragma unroll
    for (int o = 16; o > 0; o >>= 1) m = fmaxf(m, __shfl_xor_sync(0xFFFFFFFFu, m, o));
    float e = __expf(logit - m);
    float s = e;
#pragma unroll
    for (int o = 16; o > 0; o >>= 1) s += __shfl_xor_sync(0xFFFFFFFFu, s, o);
    const float prob = e / s;

    unsigned long long vpu = (unsigned long long)(uintptr_t)vp;
    float o0 = 0.f, o1 = 0.f;
#pragma unroll
    for (int j = 0; j < NKEY; j++) {
        float pj = __shfl_sync(0xFFFFFFFFu, prob, j);
        unsigned long long up = __shfl_sync(0xFFFFFFFFu, vpu, j);
        const float* vr = (const float*)(uintptr_t)up;
        o0 += pj * vr[lane];
        o1 += pj * vr[lane + 32];
    }
    ob[(size_t)p * DM + hdim + lane] = o0;
    ob[(size_t)p * DM + hdim + 32 + lane] = o1;
}

// ---------------------------------------------------------------------------
// Global attention, split-KV (proven ~24 us).
// ---------------------------------------------------------------------------
__global__ __launch_bounds__(128)
void global_attn_part_kernel(const float* __restrict__ qb, const float* __restrict__ kb,
                             const float* __restrict__ vb) {
    __shared__ float qsh[HD];
    __shared__ float le[128];
    __shared__ float red[128];

    const int c = blockIdx.x;
    const int ph = blockIdx.y;
    const int h = ph & (NH - 1);
    const int p = (ph >> 4) ? (SEQ - 1) : 0;
    const int t = threadIdx.x;
    const int j0 = c * 128;

    if (t < HD / 4)
        ((float4*)qsh)[t] = *(const float4*)(qb + (size_t)p * DM + h * HD + t * 4);
    __syncthreads();

    const float* kr = kb + (size_t)(j0 + t) * DM + h * HD;
    float a = 0.f;
#pragma unroll
    for (int cc = 0; cc < 16; cc++) {
        float4 kv = ((const float4*)kr)[cc];
        float4 qv = ((const float4*)qsh)[cc];
        a += kv.x * qv.x + kv.y * qv.y + kv.z * qv.z + kv.w * qv.w;
    }
    float logit = a * 0.125f;

    red[t] = logit; __syncthreads();
#pragma unroll
    for (int o = 64; o > 0; o >>= 1) {
        if (t < o) red[t] = fmaxf(red[t], red[t + o]);
        __syncthreads();
    }
    const float m = red[0];
    __syncthreads();

    float e = __expf(logit - m);
    le[t] = e;
    red[t] = e; __syncthreads();
#pragma unroll
    for (int o = 64; o > 0; o >>= 1) {
        if (t < o) red[t] += red[t + o];
        __syncthreads();
    }
    const float s = red[0];
    __syncthreads();

    const int d = t & (HD - 1);
    const int half = t >> 6;
    float o = 0.f;
#pragma unroll 4
    for (int j = half * 64; j < half * 64 + 64; j++)
        o += le[j] * vb[(size_t)(j0 + j) * DM + h * HD + d];
    red[t] = o; __syncthreads();
    if (t < HD)
        g_po[ph][c][t] = red[t] + red[t + 64];
    if (t == 0) { g_pm[ph][c] = m; g_ps[ph][c] = s; }
}

__global__ __launch_bounds__(64)
void global_attn_merge_kernel(float* __restrict__ ob) {
    const int ph = blockIdx.x;
    const int h = ph & (NH - 1);
    const int p = (ph >> 4) ? (SEQ - 1) : 0;
    const int t = threadIdx.x;

    float M = -1e30f;
#pragma unroll
    for (int i = 0; i < GCH; i++) M = fmaxf(M, g_pm[ph][i]);
    float S = 0.f, O = 0.f;
#pragma unroll
    for (int i = 0; i < GCH; i++) {
        float w = __expf(g_pm[ph][i] - M);
        S += w * g_ps[ph][i];
        O += w * g_po[ph][i][t];
    }
    ob[(size_t)p * DM + h * HD + t] = O / S;
}

// ---------------------------------------------------------------------------
// Launch. ncu profiles the 4th launch -> first gemm_v5 (Q projection).
// ---------------------------------------------------------------------------
extern "C" void kernel_launch(void* const* d_in, const int* in_sizes, int n_in,
                              void* d_out, int out_size) {
    const float* Q  = (const float*)d_in[0];
    const float* K  = (const float*)d_in[1];
    const float* V  = (const float*)d_in[2];
    const float* Wq = (const float*)d_in[3];
    const float* Wk = (const float*)d_in[4];
    const float* Wv = (const float*)d_in[5];
    const float* Wo = (const float*)d_in[6];
    const void*  idx = d_in[7];
    float* out = (float*)d_out;

    float *q, *k, *v, *attn, *qp, *kp, *vp, *attnp, *wqp, *wkp, *wvp, *wop;
    cudaGetSymbolAddress((void**)&q,     g_q);
    cudaGetSymbolAddress((void**)&k,     g_k);
    cudaGetSymbolAddress((void**)&v,     g_v);
    cudaGetSymbolAddress((void**)&attn,  g_attn);
    cudaGetSymbolAddress((void**)&qp,    g_qp);
    cudaGetSymbolAddress((void**)&kp,    g_kp);
    cudaGetSymbolAddress((void**)&vp,    g_vp);
    cudaGetSymbolAddress((void**)&attnp, g_attnp);
    cudaGetSymbolAddress((void**)&wqp,   g_wqp);
    cudaGetSymbolAddress((void**)&wkp,   g_wkp);
    cudaGetSymbolAddress((void**)&wvp,   g_wvp);
    cudaGetSymbolAddress((void**)&wop,   g_wop);

    cudaFuncSetAttribute(gemm_v5_kernel, cudaFuncAttributeMaxDynamicSharedMemorySize, GEMM_SMEM);

    detect_idx_kernel<<<1, 1>>>((const int*)idx);                              // 1
    dim3 gw(256, 1, 4);
    perm_w_kernel<<<gw, 256>>>(Wq, wqp, Wk, wkp, Wv, wvp, Wo, wop);            // 2
    dim3 ga(1024, 1, 3);
    perm_a_kernel<<<ga, 256>>>(Q, qp, K, kp, V, vp);                           // 3

    dim3 gg(8, 32);
    gemm_v5_kernel<<<gg, 256, GEMM_SMEM>>>(qp, wqp, q);                        // 4 (profiled)
    gemm_v5_kernel<<<gg, 256, GEMM_SMEM>>>(kp, wkp, k);                        // 5
    gemm_v5_kernel<<<gg, 256, GEMM_SMEM>>>(vp, wvp, v);                        // 6

    dim3 gsp((NNG + TQ - 1) / TQ, NH / 2);
    sparse_attn_kernel<<<gsp, 512>>>(q, k, v, idx, attn);                      // 7

    dim3 gga(GCH, 32);
    global_attn_part_kernel<<<gga, 128>>>(q, k, v);                            // 8
    global_attn_merge_kernel<<<32, 64>>>(attn);                                // 9

    dim3 ga1(1024, 1, 1);
    perm_a_kernel<<<ga1, 256>>>(attn, attnp, attn, attnp, attn, attnp);        // 10
    gemm_v5_kernel<<<gg, 256, GEMM_SMEM>>>(attnp, wop, out);                   // 11
}

// round 9
// speedup vs baseline: 1.4489x; 1.0415x over previous
#include <cuda_runtime.h>
#include <cstdint>
#include <cstddef>

#define SEQ 4096
#define DM  1024
#define NH  16
#define HD  64
#define NKEY 32
#define NNG 4094

// Scratch (device globals: allocation-free)
__device__ float g_q[SEQ * DM];
__device__ float g_k[SEQ * DM];
__device__ float g_v[SEQ * DM];
__device__ float g_attn[SEQ * DM];
__device__ float g_qp[SEQ * DM];      // permuted+rounded A operands
__device__ float g_kp[SEQ * DM];
__device__ float g_vp[SEQ * DM];
__device__ float g_attnp[SEQ * DM];
__device__ float g_wqp[DM * DM];      // permuted+rounded weights [kt][n][16]
__device__ float g_wkp[DM * DM];
__device__ float g_wvp[DM * DM];
__device__ float g_wop[DM * DM];
__device__ int   g_idx_is64;

#define GCH 32
__device__ float g_pm[32][GCH];
__device__ float g_ps[32][GCH];
__device__ float g_po[32][GCH][HD];

// ---------------------------------------------------------------------------
__global__ void detect_idx_kernel(const int* __restrict__ idx32) {
    g_idx_is64 = ((idx32[1] | idx32[3] | idx32[5] | idx32[7]) == 0) ? 1 : 0;
}

// ---------------------------------------------------------------------------
// Helpers
// ---------------------------------------------------------------------------
__device__ __forceinline__ uint32_t f2tf32(float x) {
    uint32_t r;
    asm("cvt.rna.tf32.f32 %0, %1;" : "=r"(r) : "f"(x));
    return r;
}
__device__ __forceinline__ float rndf(float x) { return __uint_as_float(f2tf32(x)); }

__device__ __forceinline__ uint32_t smem_u32(const void* p) {
    uint32_t a;
    asm("{ .reg .u64 t; cvta.to.shared.u64 t, %1; cvt.u32.u64 %0, t; }" : "=r"(a) : "l"(p));
    return a;
}
__device__ __forceinline__ void cp16(uint32_t dst, const void* src) {
    asm volatile("cp.async.cg.shared.global [%0], [%1], 16;" :: "r"(dst), "l"(src));
}
__device__ __forceinline__ void mma_tf32(float c[4], const uint32_t a[4], const uint32_t b[2]) {
    asm volatile(
        "mma.sync.aligned.m16n8k8.row.col.f32.tf32.tf32.f32 "
        "{%0,%1,%2,%3}, {%4,%5,%6,%7}, {%8,%9}, {%0,%1,%2,%3};"
        : "+f"(c[0]), "+f"(c[1]), "+f"(c[2]), "+f"(c[3])
        : "r"(a[0]), "r"(a[1]), "r"(a[2]), "r"(a[3]),
          "r"(b[0]), "r"(b[1]));
}

// ---------------------------------------------------------------------------
// Fused permute+round.
// z = 0..2: A-operand permute (Q,K,V): per row, per 16-k chunk, value k ->
//           position ((k%4)^xa)*4 + k/4, xa=(row>>1)&3. 1024 blocks used.
// z = 3..6: weight permute: Wp[kt][n][(k%4)*4+k/4] = rnd(W[kt*16+k][n]).
//           First 256 blocks used.
// ---------------------------------------------------------------------------
__global__ __launch_bounds__(256)
void perm_all_kernel(const float* __restrict__ s0, float* __restrict__ d0,
                     const float* __restrict__ s1, float* __restrict__ d1,
                     const float* __restrict__ s2, float* __restrict__ d2,
                     const float* __restrict__ w0, float* __restrict__ p0,
                     const float* __restrict__ w1, float* __restrict__ p1,
                     const float* __restrict__ w2, float* __restrict__ p2,
                     const float* __restrict__ w3, float* __restrict__ p3) {
    const int z = blockIdx.z;
    if (z < 3) {
        const float* src = (z == 0) ? s0 : (z == 1) ? s1 : s2;
        float*       dst = (z == 0) ? d0 : (z == 1) ? d1 : d2;
        const int idx = blockIdx.x * 256 + threadIdx.x;
        const int row = idx >> 6, ch = idx & 63;
        const float4* s = (const float4*)(src + (size_t)row * DM + ch * 16);
        float4 u0 = s[0], u1 = s[1], u2 = s[2], u3 = s[3];
        float vv[16] = { u0.x,u0.y,u0.z,u0.w, u1.x,u1.y,u1.z,u1.w,
                         u2.x,u2.y,u2.z,u2.w, u3.x,u3.y,u3.z,u3.w };
        const int xa = (row >> 1) & 3;
        float4* d = (float4*)(dst + (size_t)row * DM + ch * 16);
#pragma unroll
        for (int x = 0; x < 4; x++) {
            const int kq = x ^ xa;
            float4 o;
            o.x = rndf(vv[kq]); o.y = rndf(vv[kq + 4]);
            o.z = rndf(vv[kq + 8]); o.w = rndf(vv[kq + 12]);
            d[x] = o;
        }
    } else {
        if (blockIdx.x >= 256) return;
        const int zi = z - 3;
        const float* W = (zi == 0) ? w0 : (zi == 1) ? w1 : (zi == 2) ? w2 : w3;
        float*       P = (zi == 0) ? p0 : (zi == 1) ? p1 : (zi == 2) ? p2 : p3;
        const int idx = blockIdx.x * 256 + threadIdx.x;
        const int kt = idx >> 10, n = idx & 1023;
        float out[16];
#pragma unroll
        for (int k = 0; k < 16; k++)
            out[((k & 3) << 2) + (k >> 2)] = rndf(W[(size_t)(kt * 16 + k) * DM + n]);
        float4* d = (float4*)(P + (size_t)kt * (DM * 16) + (size_t)n * 16);
#pragma unroll
        for (int x = 0; x < 4; x++)
            d[x] = make_float4(out[4 * x], out[4 * x + 1], out[4 * x + 2], out[4 * x + 3]);
    }
}

// ---------------------------------------------------------------------------
// GEMM v5 (fused): C = Ap * Wp^T, z selects operand triple. 128x128 tile,
// BK=16, 256 thr = 8 warps (2M x 4N), warp tile 64x32, cp.async 3-stage,
// pre-permuted operands, 2 CTA/SM.
// ---------------------------------------------------------------------------
#define STG 16384
#define GEMM_SMEM (3 * STG)

__device__ __forceinline__ void gemm_issue(uint32_t sb, int s, int t,
                                           const float* Arow, const float* Bkt) {
    const uint32_t ab = sb + s * STG;
    const uint32_t bb = ab + 8192;
#pragma unroll
    for (int i = 0; i < 2; i++) {
        const int ch = t + (i << 8);
        cp16(ab + ch * 16, Arow + (size_t)(ch >> 2) * DM + (ch & 3) * 4);
        cp16(bb + ch * 16, Bkt + ch * 4);
    }
    asm volatile("cp.async.commit_group;" ::: "memory");
}

__global__ void __launch_bounds__(256, 2)
gemm_v5_kernel(const float* __restrict__ A0, const float* __restrict__ W0, float* __restrict__ C0,
               const float* __restrict__ A1, const float* __restrict__ W1, float* __restrict__ C1,
               const float* __restrict__ A2, const float* __restrict__ W2, float* __restrict__ C2) {
    extern __shared__ char sm[];
    const float* Ap = (blockIdx.z == 0) ? A0 : (blockIdx.z == 1) ? A1 : A2;
    const float* Wp = (blockIdx.z == 0) ? W0 : (blockIdx.z == 1) ? W1 : W2;
    float*       C  = (blockIdx.z == 0) ? C0 : (blockIdx.z == 1) ? C1 : C2;

    const uint32_t sb = smem_u32(sm);
    const int t = threadIdx.x, lane = t & 31, warp = t >> 5;
    const int wr = warp >> 2, wc = warp & 3;
    const int bm = blockIdx.y * 128, bn = blockIdx.x * 128;

    const float* Abase = Ap + (size_t)bm * DM;
    const float* Bbase = Wp + (size_t)bn * 16;

    float acc[4][4][4];
#pragma unroll
    for (int mi = 0; mi < 4; mi++)
#pragma unroll
        for (int ni = 0; ni < 4; ni++)
#pragma unroll
            for (int e = 0; e < 4; e++) acc[mi][ni][e] = 0.f;

    gemm_issue(sb, 0, t, Abase, Bbase);
    gemm_issue(sb, 1, t, Abase + 16, Bbase + (size_t)DM * 16);

    const int NT = 64;
#pragma unroll 1
    for (int kt = 0; kt < NT; kt++) {
        const int s = kt - (kt / 3) * 3;
        if (kt < NT - 1) asm volatile("cp.async.wait_group 1;" ::: "memory");
        else             asm volatile("cp.async.wait_group 0;" ::: "memory");
        __syncthreads();

        const float4* as4 = (const float4*)(sm + s * STG);
        const float4* bs4 = (const float4*)(sm + s * STG + 8192);

        float4 bq[4];
        {
            const int c0 = wc * 32 + (lane >> 2);
            const int g = lane & 3;
#pragma unroll
            for (int ni = 0; ni < 4; ni++)
                bq[ni] = bs4[(c0 + ni * 8) * 4 + g];
        }
#pragma unroll
        for (int mi = 0; mi < 4; mi++) {
            const int rlo = wr * 64 + mi * 16 + (lane >> 2);
            const int rhi = rlo + 8;
            float4 alo = as4[rlo * 4 + (((lane & 3) ^ (rlo >> 1)) & 3)];
            float4 ahi = as4[rhi * 4 + (((lane & 3) ^ (rhi >> 1)) & 3)];
            uint32_t a0[4] = { __float_as_uint(alo.x), __float_as_uint(ahi.x),
                               __float_as_uint(alo.y), __float_as_uint(ahi.y) };
            uint32_t a1[4] = { __float_as_uint(alo.z), __float_as_uint(ahi.z),
                               __float_as_uint(alo.w), __float_as_uint(ahi.w) };
#pragma unroll
            for (int ni = 0; ni < 4; ni++) {
                uint32_t b0[2] = { __float_as_uint(bq[ni].x), __float_as_uint(bq[ni].y) };
                uint32_t b1[2] = { __float_as_uint(bq[ni].z), __float_as_uint(bq[ni].w) };
                mma_tf32(acc[mi][ni], a0, b0);
                mma_tf32(acc[mi][ni], a1, b1);
            }
        }

        if (kt + 2 < NT) {
            const int ns = (kt + 2) - ((kt + 2) / 3) * 3;
            gemm_issue(sb, ns, t, Abase + (kt + 2) * 16, Bbase + (size_t)(kt + 2) * DM * 16);
        }
    }

#pragma unroll
    for (int mi = 0; mi < 4; mi++) {
#pragma unroll
        for (int ni = 0; ni < 4; ni++) {
            const int r = bm + wr * 64 + mi * 16 + (lane >> 2);
            const int c = bn + wc * 32 + ni * 8 + ((lane & 3) << 1);
            float2 v0 = make_float2(acc[mi][ni][0], acc[mi][ni][1]);
            float2 v1 = make_float2(acc[mi][ni][2], acc[mi][ni][3]);
            *(float2*)(C + (size_t)r * DM + c) = v0;
            *(float2*)(C + (size_t)(r + 8) * DM + c) = v1;
        }
    }
}

// ---------------------------------------------------------------------------
// Sparse attention (byte-identical to round 8; PROFILED this round).
// Block = 8 adjacent queries x 2 heads (16 warps); window keys in smem.
// ---------------------------------------------------------------------------
#define TQ 8
#define WROWS 30

__global__ __launch_bounds__(512)
void sparse_attn_kernel(const float* __restrict__ qb, const float* __restrict__ kb,
                        const float* __restrict__ vb, const void* __restrict__ idxp,
                        float* __restrict__ ob) {
    __shared__ float sQ[TQ][128];
    __shared__ float sK[WROWS][128];
    __shared__ float sV[WROWS][128];

    const int t = threadIdx.x;
    const int pbase = blockIdx.x * TQ + 1;
    const int hb = blockIdx.y * 128;
    const int r0 = pbase - 11;

    if (t < 256) {
        int row = t >> 5, i = (t & 31) << 2;
        int p = pbase + row;
        if (p <= SEQ - 2)
            *(float4*)&sQ[row][i] = *(const float4*)(qb + (size_t)p * DM + hb + i);
    }
#pragma unroll
    for (int f = 0; f < 2 * WROWS * 32; f += 512) {
        int g = f + t;
        if (g < 2 * WROWS * 32) {
            int sel = (g >= WROWS * 32);
            int rem = sel ? g - WROWS * 32 : g;
            int row = rem >> 5, i = (rem & 31) << 2;
            int rg = r0 + row;
            rg = rg < 0 ? 0 : (rg > SEQ - 1 ? SEQ - 1 : rg);
            const float* src = (sel ? vb : kb) + (size_t)rg * DM + hb + i;
            float* dst = (sel ? &sV[0][0] : &sK[0][0]) + row * 128 + i;
            *(float4*)dst = *(const float4*)src;
        }
    }
    __syncthreads();

    const int warp = t >> 5, lane = t & 31;
    const int ql = warp & 7, hl = warp >> 3;
    const int p = pbase + ql;
    if (p > SEQ - 2) return;
    const int n = p - 1;
    const int hdim = hb + hl * 64;

    const float* kp;
    const float* vp;
    if (lane >= 9) {
        int rl = ql + lane - 9;
        kp = &sK[rl][hl * 64];
        vp = &sV[rl][hl * 64];
    } else {
        int row = 0;
        if (lane >= 1) {
            row = g_idx_is64
                ? (int)((const long long*)idxp)[(size_t)n * NKEY + lane]
                : ((const int*)idxp)[(size_t)n * NKEY + lane];
        }
        kp = kb + (size_t)row * DM + hdim;
        vp = vb + (size_t)row * DM + hdim;
    }
    const float* qp = &sQ[ql][hl * 64];

    float a = 0.f;
#pragma unroll
    for (int c = 0; c < 16; c++) {
        float4 kv = ((const float4*)kp)[c];
        float4 qv = ((const float4*)qp)[c];
        a += kv.x * qv.x + kv.y * qv.y + kv.z * qv.z + kv.w * qv.w;
    }
    float logit = a * 0.125f;

    float m = logit;
#pragma unroll
    for (int o = 16; o > 0; o >>= 1) m = fmaxf(m, __shfl_xor_sync(0xFFFFFFFFu, m, o));
    float e = __expf(logit - m);
    float s = e;
#pragma unroll
    for (int o = 16; o > 0; o >>= 1) s += __shfl_xor_sync(0xFFFFFFFFu, s, o);
    const float prob = e / s;

    unsigned long long vpu = (unsigned long long)(uintptr_t)vp;
    float o0 = 0.f, o1 = 0.f;
#pragma unroll
    for (int j = 0; j < NKEY; j++) {
        float pj = __shfl_sync(0xFFFFFFFFu, prob, j);
        unsigned long long up = __shfl_sync(0xFFFFFFFFu, vpu, j);
        const float* vr = (const float*)(uintptr_t)up;
        o0 += pj * vr[lane];
        o1 += pj * vr[lane + 32];
    }
    ob[(size_t)p * DM + hdim + lane] = o0;
    ob[(size_t)p * DM + hdim + 32 + lane] = o1;
}

// ---------------------------------------------------------------------------
// Global attention, split-KV (proven ~24 us).
// ---------------------------------------------------------------------------
__global__ __launch_bounds__(128)
void global_attn_part_kernel(const float* __restrict__ qb, const float* __restrict__ kb,
                             const float* __restrict__ vb) {
    __shared__ float qsh[HD];
    __shared__ float le[128];
    __shared__ float red[128];

    const int c = blockIdx.x;
    const int ph = blockIdx.y;
    const int h = ph & (NH - 1);
    const int p = (ph >> 4) ? (SEQ - 1) : 0;
    const int t = threadIdx.x;
    const int j0 = c * 128;

    if (t < HD / 4)
        ((float4*)qsh)[t] = *(const float4*)(qb + (size_t)p * DM + h * HD + t * 4);
    __syncthreads();

    const float* kr = kb + (size_t)(j0 + t) * DM + h * HD;
    float a = 0.f;
#pragma unroll
    for (int cc = 0; cc < 16; cc++) {
        float4 kv = ((const float4*)kr)[cc];
        float4 qv = ((const float4*)qsh)[cc];
        a += kv.x * qv.x + kv.y * qv.y + kv.z * qv.z + kv.w * qv.w;
    }
    float logit = a * 0.125f;

    red[t] = logit; __syncthreads();
#pragma unroll
    for (int o = 64; o > 0; o >>= 1) {
        if (t < o) red[t] = fmaxf(red[t], red[t + o]);
        __syncthreads();
    }
    const float m = red[0];
    __syncthreads();

    float e = __expf(logit - m);
    le[t] = e;
    red[t] = e; __syncthreads();
#pragma unroll
    for (int o = 64; o > 0; o >>= 1) {
        if (t < o) red[t] += red[t + o];
        __syncthreads();
    }
    const float s = red[0];
    __syncthreads();

    const int d = t & (HD - 1);
    const int half = t >> 6;
    float o = 0.f;
#pragma unroll 4
    for (int j = half * 64; j < half * 64 + 64; j++)
        o += le[j] * vb[(size_t)(j0 + j) * DM + h * HD + d];
    red[t] = o; __syncthreads();
    if (t < HD)
        g_po[ph][c][t] = red[t] + red[t + 64];
    if (t == 0) { g_pm[ph][c] = m; g_ps[ph][c] = s; }
}

__global__ __launch_bounds__(64)
void global_attn_merge_kernel(float* __restrict__ ob) {
    const int ph = blockIdx.x;
    const int h = ph & (NH - 1);
    const int p = (ph >> 4) ? (SEQ - 1) : 0;
    const int t = threadIdx.x;

    float M = -1e30f;
#pragma unroll
    for (int i = 0; i < GCH; i++) M = fmaxf(M, g_pm[ph][i]);
    float S = 0.f, O = 0.f;
#pragma unroll
    for (int i = 0; i < GCH; i++) {
        float w = __expf(g_pm[ph][i] - M);
        S += w * g_ps[ph][i];
        O += w * g_po[ph][i][t];
    }
    ob[(size_t)p * DM + h * HD + t] = O / S;
}

// ---------------------------------------------------------------------------
// A-operand permute for the attention output (single buffer).
// ---------------------------------------------------------------------------
__global__ __launch_bounds__(256)
void perm_attn_kernel(const float* __restrict__ src, float* __restrict__ dst) {
    const int idx = blockIdx.x * 256 + threadIdx.x;
    const int row = idx >> 6, ch = idx & 63;
    const float4* s = (const float4*)(src + (size_t)row * DM + ch * 16);
    float4 u0 = s[0], u1 = s[1], u2 = s[2], u3 = s[3];
    float vv[16] = { u0.x,u0.y,u0.z,u0.w, u1.x,u1.y,u1.z,u1.w,
                     u2.x,u2.y,u2.z,u2.w, u3.x,u3.y,u3.z,u3.w };
    const int xa = (row >> 1) & 3;
    float4* d = (float4*)(dst + (size_t)row * DM + ch * 16);
#pragma unroll
    for (int x = 0; x < 4; x++) {
        const int kq = x ^ xa;
        float4 o;
        o.x = rndf(vv[kq]); o.y = rndf(vv[kq + 4]);
        o.z = rndf(vv[kq + 8]); o.w = rndf(vv[kq + 12]);
        d[x] = o;
    }
}

// ---------------------------------------------------------------------------
// Launch. ncu profiles the 4th launch -> sparse_attn_kernel.
// ---------------------------------------------------------------------------
extern "C" void kernel_launch(void* const* d_in, const int* in_sizes, int n_in,
                              void* d_out, int out_size) {
    const float* Q  = (const float*)d_in[0];
    const float* K  = (const float*)d_in[1];
    const float* V  = (const float*)d_in[2];
    const float* Wq = (const float*)d_in[3];
    const float* Wk = (const float*)d_in[4];
    const float* Wv = (const float*)d_in[5];
    const float* Wo = (const float*)d_in[6];
    const void*  idx = d_in[7];
    float* out = (float*)d_out;

    float *q, *k, *v, *attn, *qp, *kp, *vp, *attnp, *wqp, *wkp, *wvp, *wop;
    cudaGetSymbolAddress((void**)&q,     g_q);
    cudaGetSymbolAddress((void**)&k,     g_k);
    cudaGetSymbolAddress((void**)&v,     g_v);
    cudaGetSymbolAddress((void**)&attn,  g_attn);
    cudaGetSymbolAddress((void**)&qp,    g_qp);
    cudaGetSymbolAddress((void**)&kp,    g_kp);
    cudaGetSymbolAddress((void**)&vp,    g_vp);
    cudaGetSymbolAddress((void**)&attnp, g_attnp);
    cudaGetSymbolAddress((void**)&wqp,   g_wqp);
    cudaGetSymbolAddress((void**)&wkp,   g_wkp);
    cudaGetSymbolAddress((void**)&wvp,   g_wvp);
    cudaGetSymbolAddress((void**)&wop,   g_wop);

    cudaFuncSetAttribute(gemm_v5_kernel, cudaFuncAttributeMaxDynamicSharedMemorySize, GEMM_SMEM);

    detect_idx_kernel<<<1, 1>>>((const int*)idx);                              // 1

    dim3 gp(1024, 1, 7);
    perm_all_kernel<<<gp, 256>>>(Q, qp, K, kp, V, vp,
                                 Wq, wqp, Wk, wkp, Wv, wvp, Wo, wop);          // 2

    dim3 gg(8, 32, 3);
    gemm_v5_kernel<<<gg, 256, GEMM_SMEM>>>(qp, wqp, q, kp, wkp, k, vp, wvp, v); // 3

    dim3 gsp((NNG + TQ - 1) / TQ, NH / 2);
    sparse_attn_kernel<<<gsp, 512>>>(q, k, v, idx, attn);                      // 4 (profiled)

    dim3 gga(GCH, 32);
    global_attn_part_kernel<<<gga, 128>>>(q, k, v);                            // 5
    global_attn_merge_kernel<<<32, 64>>>(attn);                                // 6

    perm_attn_kernel<<<1024, 256>>>(attn, attnp);                              // 7

    dim3 go(8, 32, 1);
    gemm_v5_kernel<<<go, 256, GEMM_SMEM>>>(attnp, wop, out,
                                           attnp, wop, out, attnp, wop, out);  // 8
}

// round 10
// speedup vs baseline: 1.7018x; 1.1746x over previous
#include <cuda_runtime.h>
#include <cstdint>
#include <cstddef>

#define SEQ 4096
#define DM  1024
#define NH  16
#define HD  64
#define NKEY 32
#define NNG 4094

// Scratch (device globals: allocation-free)
__device__ float g_q[SEQ * DM];
__device__ float g_k[SEQ * DM];
__device__ float g_v[SEQ * DM];
__device__ float g_attn[SEQ * DM];
__device__ float g_qp[SEQ * DM];      // permuted+rounded A operands
__device__ float g_kp[SEQ * DM];
__device__ float g_vp[SEQ * DM];
__device__ float g_attnp[SEQ * DM];
__device__ float g_wqp[DM * DM];      // permuted+rounded weights [kt][n][16]
__device__ float g_wkp[DM * DM];
__device__ float g_wvp[DM * DM];
__device__ float g_wop[DM * DM];
__device__ int   g_idx_is64;

#define GCH 32
__device__ float g_pm[32][GCH];
__device__ float g_ps[32][GCH];
__device__ float g_po[32][GCH][HD];

// ---------------------------------------------------------------------------
__global__ void detect_idx_kernel(const int* __restrict__ idx32) {
    g_idx_is64 = ((idx32[1] | idx32[3] | idx32[5] | idx32[7]) == 0) ? 1 : 0;
}

// ---------------------------------------------------------------------------
// Helpers
// ---------------------------------------------------------------------------
__device__ __forceinline__ uint32_t f2tf32(float x) {
    uint32_t r;
    asm("cvt.rna.tf32.f32 %0, %1;" : "=r"(r) : "f"(x));
    return r;
}
__device__ __forceinline__ float rndf(float x) { return __uint_as_float(f2tf32(x)); }

__device__ __forceinline__ uint32_t smem_u32(const void* p) {
    uint32_t a;
    asm("{ .reg .u64 t; cvta.to.shared.u64 t, %1; cvt.u32.u64 %0, t; }" : "=r"(a) : "l"(p));
    return a;
}
__device__ __forceinline__ void cp16(uint32_t dst, const void* src) {
    asm volatile("cp.async.cg.shared.global [%0], [%1], 16;" :: "r"(dst), "l"(src));
}
__device__ __forceinline__ void mma_tf32(float c[4], const uint32_t a[4], const uint32_t b[2]) {
    asm volatile(
        "mma.sync.aligned.m16n8k8.row.col.f32.tf32.tf32.f32 "
        "{%0,%1,%2,%3}, {%4,%5,%6,%7}, {%8,%9}, {%0,%1,%2,%3};"
        : "+f"(c[0]), "+f"(c[1]), "+f"(c[2]), "+f"(c[3])
        : "r"(a[0]), "r"(a[1]), "r"(a[2]), "r"(a[3]),
          "r"(b[0]), "r"(b[1]));
}

// ---------------------------------------------------------------------------
// Fused permute+round (z=0..2: A operands; z=3..6: weights).
// ---------------------------------------------------------------------------
__global__ __launch_bounds__(256)
void perm_all_kernel(const float* __restrict__ s0, float* __restrict__ d0,
                     const float* __restrict__ s1, float* __restrict__ d1,
                     const float* __restrict__ s2, float* __restrict__ d2,
                     const float* __restrict__ w0, float* __restrict__ p0,
                     const float* __restrict__ w1, float* __restrict__ p1,
                     const float* __restrict__ w2, float* __restrict__ p2,
                     const float* __restrict__ w3, float* __restrict__ p3) {
    const int z = blockIdx.z;
    if (z < 3) {
        const float* src = (z == 0) ? s0 : (z == 1) ? s1 : s2;
        float*       dst = (z == 0) ? d0 : (z == 1) ? d1 : d2;
        const int idx = blockIdx.x * 256 + threadIdx.x;
        const int row = idx >> 6, ch = idx & 63;
        const float4* s = (const float4*)(src + (size_t)row * DM + ch * 16);
        float4 u0 = s[0], u1 = s[1], u2 = s[2], u3 = s[3];
        float vv[16] = { u0.x,u0.y,u0.z,u0.w, u1.x,u1.y,u1.z,u1.w,
                         u2.x,u2.y,u2.z,u2.w, u3.x,u3.y,u3.z,u3.w };
        const int xa = (row >> 1) & 3;
        float4* d = (float4*)(dst + (size_t)row * DM + ch * 16);
#pragma unroll
        for (int x = 0; x < 4; x++) {
            const int kq = x ^ xa;
            float4 o;
            o.x = rndf(vv[kq]); o.y = rndf(vv[kq + 4]);
            o.z = rndf(vv[kq + 8]); o.w = rndf(vv[kq + 12]);
            d[x] = o;
        }
    } else {
        if (blockIdx.x >= 256) return;
        const int zi = z - 3;
        const float* W = (zi == 0) ? w0 : (zi == 1) ? w1 : (zi == 2) ? w2 : w3;
        float*       P = (zi == 0) ? p0 : (zi == 1) ? p1 : (zi == 2) ? p2 : p3;
        const int idx = blockIdx.x * 256 + threadIdx.x;
        const int kt = idx >> 10, n = idx & 1023;
        float out[16];
#pragma unroll
        for (int k = 0; k < 16; k++)
            out[((k & 3) << 2) + (k >> 2)] = rndf(W[(size_t)(kt * 16 + k) * DM + n]);
        float4* d = (float4*)(P + (size_t)kt * (DM * 16) + (size_t)n * 16);
#pragma unroll
        for (int x = 0; x < 4; x++)
            d[x] = make_float4(out[4 * x], out[4 * x + 1], out[4 * x + 2], out[4 * x + 3]);
    }
}

// ---------------------------------------------------------------------------
// GEMM v5 (fused): C = Ap * Wp^T, z selects operand triple. 128x128 tile,
// BK=16, 256 thr = 8 warps (2M x 4N), warp tile 64x32, cp.async 3-stage.
// ---------------------------------------------------------------------------
#define STG 16384
#define GEMM_SMEM (3 * STG)

__device__ __forceinline__ void gemm_issue(uint32_t sb, int s, int t,
                                           const float* Arow, const float* Bkt) {
    const uint32_t ab = sb + s * STG;
    const uint32_t bb = ab + 8192;
#pragma unroll
    for (int i = 0; i < 2; i++) {
        const int ch = t + (i << 8);
        cp16(ab + ch * 16, Arow + (size_t)(ch >> 2) * DM + (ch & 3) * 4);
        cp16(bb + ch * 16, Bkt + ch * 4);
    }
    asm volatile("cp.async.commit_group;" ::: "memory");
}

__global__ void __launch_bounds__(256, 2)
gemm_v5_kernel(const float* __restrict__ A0, const float* __restrict__ W0, float* __restrict__ C0,
               const float* __restrict__ A1, const float* __restrict__ W1, float* __restrict__ C1,
               const float* __restrict__ A2, const float* __restrict__ W2, float* __restrict__ C2) {
    extern __shared__ char sm[];
    const float* Ap = (blockIdx.z == 0) ? A0 : (blockIdx.z == 1) ? A1 : A2;
    const float* Wp = (blockIdx.z == 0) ? W0 : (blockIdx.z == 1) ? W1 : W2;
    float*       C  = (blockIdx.z == 0) ? C0 : (blockIdx.z == 1) ? C1 : C2;

    const uint32_t sb = smem_u32(sm);
    const int t = threadIdx.x, lane = t & 31, warp = t >> 5;
    const int wr = warp >> 2, wc = warp & 3;
    const int bm = blockIdx.y * 128, bn = blockIdx.x * 128;

    const float* Abase = Ap + (size_t)bm * DM;
    const float* Bbase = Wp + (size_t)bn * 16;

    float acc[4][4][4];
#pragma unroll
    for (int mi = 0; mi < 4; mi++)
#pragma unroll
        for (int ni = 0; ni < 4; ni++)
#pragma unroll
            for (int e = 0; e < 4; e++) acc[mi][ni][e] = 0.f;

    gemm_issue(sb, 0, t, Abase, Bbase);
    gemm_issue(sb, 1, t, Abase + 16, Bbase + (size_t)DM * 16);

    const int NT = 64;
#pragma unroll 1
    for (int kt = 0; kt < NT; kt++) {
        const int s = kt - (kt / 3) * 3;
        if (kt < NT - 1) asm volatile("cp.async.wait_group 1;" ::: "memory");
        else             asm volatile("cp.async.wait_group 0;" ::: "memory");
        __syncthreads();

        const float4* as4 = (const float4*)(sm + s * STG);
        const float4* bs4 = (const float4*)(sm + s * STG + 8192);

        float4 bq[4];
        {
            const int c0 = wc * 32 + (lane >> 2);
            const int g = lane & 3;
#pragma unroll
            for (int ni = 0; ni < 4; ni++)
                bq[ni] = bs4[(c0 + ni * 8) * 4 + g];
        }
#pragma unroll
        for (int mi = 0; mi < 4; mi++) {
            const int rlo = wr * 64 + mi * 16 + (lane >> 2);
            const int rhi = rlo + 8;
            float4 alo = as4[rlo * 4 + (((lane & 3) ^ (rlo >> 1)) & 3)];
            float4 ahi = as4[rhi * 4 + (((lane & 3) ^ (rhi >> 1)) & 3)];
            uint32_t a0[4] = { __float_as_uint(alo.x), __float_as_uint(ahi.x),
                               __float_as_uint(alo.y), __float_as_uint(ahi.y) };
            uint32_t a1[4] = { __float_as_uint(alo.z), __float_as_uint(ahi.z),
                               __float_as_uint(alo.w), __float_as_uint(ahi.w) };
#pragma unroll
            for (int ni = 0; ni < 4; ni++) {
                uint32_t b0[2] = { __float_as_uint(bq[ni].x), __float_as_uint(bq[ni].y) };
                uint32_t b1[2] = { __float_as_uint(bq[ni].z), __float_as_uint(bq[ni].w) };
                mma_tf32(acc[mi][ni], a0, b0);
                mma_tf32(acc[mi][ni], a1, b1);
            }
        }

        if (kt + 2 < NT) {
            const int ns = (kt + 2) - ((kt + 2) / 3) * 3;
            gemm_issue(sb, ns, t, Abase + (kt + 2) * 16, Bbase + (size_t)(kt + 2) * DM * 16);
        }
    }

#pragma unroll
    for (int mi = 0; mi < 4; mi++) {
#pragma unroll
        for (int ni = 0; ni < 4; ni++) {
            const int r = bm + wr * 64 + mi * 16 + (lane >> 2);
            const int c = bn + wc * 32 + ni * 8 + ((lane & 3) << 1);
            float2 v0 = make_float2(acc[mi][ni][0], acc[mi][ni][1]);
            float2 v1 = make_float2(acc[mi][ni][2], acc[mi][ni][3]);
            *(float2*)(C + (size_t)r * DM + c) = v0;
            *(float2*)(C + (size_t)(r + 8) * DM + c) = v1;
        }
    }
}

// ---------------------------------------------------------------------------
// Sparse attention. Round-10 change: window tiles padded [WROWS][132]
// (row stride 528B = 33 x 16B super-banks, 33 mod 8 = 1) so the 23 window
// lanes reading different rows at the same column hit DISTINCT super-banks.
// Was [WROWS][128] (stride 512B -> all lanes same super-bank, ~23-way
// conflict per LDS.128 -> L1 88.5% busy).
// ---------------------------------------------------------------------------
#define TQ 8
#define WROWS 30
#define WPAD 132

__global__ __launch_bounds__(512)
void sparse_attn_kernel(const float* __restrict__ qb, const float* __restrict__ kb,
                        const float* __restrict__ vb, const void* __restrict__ idxp,
                        float* __restrict__ ob) {
    __shared__ float sQ[TQ][128];
    __shared__ float sK[WROWS][WPAD];
    __shared__ float sV[WROWS][WPAD];

    const int t = threadIdx.x;
    const int pbase = blockIdx.x * TQ + 1;
    const int hb = blockIdx.y * 128;
    const int r0 = pbase - 11;

    if (t < 256) {
        int row = t >> 5, i = (t & 31) << 2;
        int p = pbase + row;
        if (p <= SEQ - 2)
            *(float4*)&sQ[row][i] = *(const float4*)(qb + (size_t)p * DM + hb + i);
    }
#pragma unroll
    for (int f = 0; f < 2 * WROWS * 32; f += 512) {
        int g = f + t;
        if (g < 2 * WROWS * 32) {
            int sel = (g >= WROWS * 32);
            int rem = sel ? g - WROWS * 32 : g;
            int row = rem >> 5, i = (rem & 31) << 2;
            int rg = r0 + row;
            rg = rg < 0 ? 0 : (rg > SEQ - 1 ? SEQ - 1 : rg);
            const float* src = (sel ? vb : kb) + (size_t)rg * DM + hb + i;
            float* dst = (sel ? &sV[0][0] : &sK[0][0]) + row * WPAD + i;
            *(float4*)dst = *(const float4*)src;
        }
    }
    __syncthreads();

    const int warp = t >> 5, lane = t & 31;
    const int ql = warp & 7, hl = warp >> 3;
    const int p = pbase + ql;
    if (p > SEQ - 2) return;
    const int n = p - 1;
    const int hdim = hb + hl * 64;

    const float* kp;
    const float* vp;
    if (lane >= 9) {
        int rl = ql + lane - 9;
        kp = &sK[rl][hl * 64];
        vp = &sV[rl][hl * 64];
    } else {
        int row = 0;
        if (lane >= 1) {
            row = g_idx_is64
                ? (int)((const long long*)idxp)[(size_t)n * NKEY + lane]
                : ((const int*)idxp)[(size_t)n * NKEY + lane];
        }
        kp = kb + (size_t)row * DM + hdim;
        vp = vb + (size_t)row * DM + hdim;
    }
    const float* qp = &sQ[ql][hl * 64];

    float a = 0.f;
#pragma unroll
    for (int c = 0; c < 16; c++) {
        float4 kv = ((const float4*)kp)[c];
        float4 qv = ((const float4*)qp)[c];
        a += kv.x * qv.x + kv.y * qv.y + kv.z * qv.z + kv.w * qv.w;
    }
    float logit = a * 0.125f;

    float m = logit;
#pragma unroll
    for (int o = 16; o > 0; o >>= 1) m = fmaxf(m, __shfl_xor_sync(0xFFFFFFFFu, m, o));
    float e = __expf(logit - m);
    float s = e;
#pragma unroll
    for (int o = 16; o > 0; o >>= 1) s += __shfl_xor_sync(0xFFFFFFFFu, s, o);
    const float prob = e / s;

    unsigned long long vpu = (unsigned long long)(uintptr_t)vp;
    float o0 = 0.f, o1 = 0.f;
#pragma unroll
    for (int j = 0; j < NKEY; j++) {
        float pj = __shfl_sync(0xFFFFFFFFu, prob, j);
        unsigned long long up = __shfl_sync(0xFFFFFFFFu, vpu, j);
        const float* vr = (const float*)(uintptr_t)up;
        o0 += pj * vr[lane];
        o1 += pj * vr[lane + 32];
    }
    ob[(size_t)p * DM + hdim + lane] = o0;
    ob[(size_t)p * DM + hdim + 32 + lane] = o1;
}

// ---------------------------------------------------------------------------
// Global attention, split-KV (proven ~24 us).
// ---------------------------------------------------------------------------
__global__ __launch_bounds__(128)
void global_attn_part_kernel(const float* __restrict__ qb, const float* __restrict__ kb,
                             const float* __restrict__ vb) {
    __shared__ float qsh[HD];
    __shared__ float le[128];
    __shared__ float red[128];

    const int c = blockIdx.x;
    const int ph = blockIdx.y;
    const int h = ph & (NH - 1);
    const int p = (ph >> 4) ? (SEQ - 1) : 0;
    const int t = threadIdx.x;
    const int j0 = c * 128;

    if (t < HD / 4)
        ((float4*)qsh)[t] = *(const float4*)(qb + (size_t)p * DM + h * HD + t * 4);
    __syncthreads();

    const float* kr = kb + (size_t)(j0 + t) * DM + h * HD;
    float a = 0.f;
#pragma unroll
    for (int cc = 0; cc < 16; cc++) {
        float4 kv = ((const float4*)kr)[cc];
        float4 qv = ((const float4*)qsh)[cc];
        a += kv.x * qv.x + kv.y * qv.y + kv.z * qv.z + kv.w * qv.w;
    }
    float logit = a * 0.125f;

    red[t] = logit; __syncthreads();
#pragma unroll
    for (int o = 64; o > 0; o >>= 1) {
        if (t < o) red[t] = fmaxf(red[t], red[t + o]);
        __syncthreads();
    }
    const float m = red[0];
    __syncthreads();

    float e = __expf(logit - m);
    le[t] = e;
    red[t] = e; __syncthreads();
#pragma unroll
    for (int o = 64; o > 0; o >>= 1) {
        if (t < o) red[t] += red[t + o];
        __syncthreads();
    }
    const float s = red[0];
    __syncthreads();

    const int d = t & (HD - 1);
    const int half = t >> 6;
    float o = 0.f;
#pragma unroll 4
    for (int j = half * 64; j < half * 64 + 64; j++)
        o += le[j] * vb[(size_t)(j0 + j) * DM + h * HD + d];
    red[t] = o; __syncthreads();
    if (t < HD)
        g_po[ph][c][t] = red[t] + red[t + 64];
    if (t == 0) { g_pm[ph][c] = m; g_ps[ph][c] = s; }
}

__global__ __launch_bounds__(64)
void global_attn_merge_kernel(float* __restrict__ ob) {
    const int ph = blockIdx.x;
    const int h = ph & (NH - 1);
    const int p = (ph >> 4) ? (SEQ - 1) : 0;
    const int t = threadIdx.x;

    float M = -1e30f;
#pragma unroll
    for (int i = 0; i < GCH; i++) M = fmaxf(M, g_pm[ph][i]);
    float S = 0.f, O = 0.f;
#pragma unroll
    for (int i = 0; i < GCH; i++) {
        float w = __expf(g_pm[ph][i] - M);
        S += w * g_ps[ph][i];
        O += w * g_po[ph][i][t];
    }
    ob[(size_t)p * DM + h * HD + t] = O / S;
}

// ---------------------------------------------------------------------------
// A-operand permute for the attention output (single buffer).
// ---------------------------------------------------------------------------
__global__ __launch_bounds__(256)
void perm_attn_kernel(const float* __restrict__ src, float* __restrict__ dst) {
    const int idx = blockIdx.x * 256 + threadIdx.x;
    const int row = idx >> 6, ch = idx & 63;
    const float4* s = (const float4*)(src + (size_t)row * DM + ch * 16);
    float4 u0 = s[0], u1 = s[1], u2 = s[2], u3 = s[3];
    float vv[16] = { u0.x,u0.y,u0.z,u0.w, u1.x,u1.y,u1.z,u1.w,
                     u2.x,u2.y,u2.z,u2.w, u3.x,u3.y,u3.z,u3.w };
    const int xa = (row >> 1) & 3;
    float4* d = (float4*)(dst + (size_t)row * DM + ch * 16);
#pragma unroll
    for (int x = 0; x < 4; x++) {
        const int kq = x ^ xa;
        float4 o;
        o.x = rndf(vv[kq]); o.y = rndf(vv[kq + 4]);
        o.z = rndf(vv[kq + 8]); o.w = rndf(vv[kq + 12]);
        d[x] = o;
    }
}

// ---------------------------------------------------------------------------
// Launch. ncu profiles the 4th launch -> sparse_attn_kernel.
// ---------------------------------------------------------------------------
extern "C" void kernel_launch(void* const* d_in, const int* in_sizes, int n_in,
                              void* d_out, int out_size) {
    const float* Q  = (const float*)d_in[0];
    const float* K  = (const float*)d_in[1];
    const float* V  = (const float*)d_in[2];
    const float* Wq = (const float*)d_in[3];
    const float* Wk = (const float*)d_in[4];
    const float* Wv = (const float*)d_in[5];
    const float* Wo = (const float*)d_in[6];
    const void*  idx = d_in[7];
    float* out = (float*)d_out;

    float *q, *k, *v, *attn, *qp, *kp, *vp, *attnp, *wqp, *wkp, *wvp, *wop;
    cudaGetSymbolAddress((void**)&q,     g_q);
    cudaGetSymbolAddress((void**)&k,     g_k);
    cudaGetSymbolAddress((void**)&v,     g_v);
    cudaGetSymbolAddress((void**)&attn,  g_attn);
    cudaGetSymbolAddress((void**)&qp,    g_qp);
    cudaGetSymbolAddress((void**)&kp,    g_kp);
    cudaGetSymbolAddress((void**)&vp,    g_vp);
    cudaGetSymbolAddress((void**)&attnp, g_attnp);
    cudaGetSymbolAddress((void**)&wqp,   g_wqp);
    cudaGetSymbolAddress((void**)&wkp,   g_wkp);
    cudaGetSymbolAddress((void**)&wvp,   g_wvp);
    cudaGetSymbolAddress((void**)&wop,   g_wop);

    cudaFuncSetAttribute(gemm_v5_kernel, cudaFuncAttributeMaxDynamicSharedMemorySize, GEMM_SMEM);

    detect_idx_kernel<<<1, 1>>>((const int*)idx);                              // 1

    dim3 gp(1024, 1, 7);
    perm_all_kernel<<<gp, 256>>>(Q, qp, K, kp, V, vp,
                                 Wq, wqp, Wk, wkp, Wv, wvp, Wo, wop);          // 2

    dim3 gg(8, 32, 3);
    gemm_v5_kernel<<<gg, 256, GEMM_SMEM>>>(qp, wqp, q, kp, wkp, k, vp, wvp, v); // 3

    dim3 gsp((NNG + TQ - 1) / TQ, NH / 2);
    sparse_attn_kernel<<<gsp, 512>>>(q, k, v, idx, attn);                      // 4 (profiled)

    dim3 gga(GCH, 32);
    global_attn_part_kernel<<<gga, 128>>>(q, k, v);                            // 5
    global_attn_merge_kernel<<<32, 64>>>(attn);                                // 6

    perm_attn_kernel<<<1024, 256>>>(attn, attnp);                              // 7

    dim3 go(8, 32, 1);
    gemm_v5_kernel<<<go, 256, GEMM_SMEM>>>(attnp, wop, out,
                                           attnp, wop, out, attnp, wop, out);  // 8
}

// round 11
// speedup vs baseline: 1.7776x; 1.0445x over previous
#include <cuda_runtime.h>
#include <cstdint>
#include <cstddef>

#define SEQ 4096
#define DM  1024
#define NH  16
#define HD  64
#define NKEY 32
#define NNG 4094

// Scratch (device globals: allocation-free)
__device__ float g_q[SEQ * DM];
__device__ float g_k[SEQ * DM];
__device__ float g_v[SEQ * DM];
__device__ float g_qp[SEQ * DM];      // permuted+rounded A operands
__device__ float g_kp[SEQ * DM];
__device__ float g_vp[SEQ * DM];
__device__ float g_attnp[SEQ * DM];   // attention out, permuted+rounded
__device__ float g_wqp[DM * DM];      // permuted+rounded weights [kt][n][16]
__device__ float g_wkp[DM * DM];
__device__ float g_wvp[DM * DM];
__device__ float g_wop[DM * DM];
__device__ int   g_idx_is64;

#define GCH 32
__device__ float g_pm[32][GCH];
__device__ float g_ps[32][GCH];
__device__ float g_po[32][GCH][HD];

// ---------------------------------------------------------------------------
__global__ void detect_idx_kernel(const int* __restrict__ idx32) {
    g_idx_is64 = ((idx32[1] | idx32[3] | idx32[5] | idx32[7]) == 0) ? 1 : 0;
}

// ---------------------------------------------------------------------------
// Helpers
// ---------------------------------------------------------------------------
__device__ __forceinline__ uint32_t f2tf32(float x) {
    uint32_t r;
    asm("cvt.rna.tf32.f32 %0, %1;" : "=r"(r) : "f"(x));
    return r;
}
__device__ __forceinline__ float rndf(float x) { return __uint_as_float(f2tf32(x)); }

__device__ __forceinline__ uint32_t smem_u32(const void* p) {
    uint32_t a;
    asm("{ .reg .u64 t; cvta.to.shared.u64 t, %1; cvt.u32.u64 %0, t; }" : "=r"(a) : "l"(p));
    return a;
}
__device__ __forceinline__ void cp16(uint32_t dst, const void* src) {
    asm volatile("cp.async.cg.shared.global [%0], [%1], 16;" :: "r"(dst), "l"(src));
}
__device__ __forceinline__ void mma_tf32(float c[4], const uint32_t a[4], const uint32_t b[2]) {
    asm volatile(
        "mma.sync.aligned.m16n8k8.row.col.f32.tf32.tf32.f32 "
        "{%0,%1,%2,%3}, {%4,%5,%6,%7}, {%8,%9}, {%0,%1,%2,%3};"
        : "+f"(c[0]), "+f"(c[1]), "+f"(c[2]), "+f"(c[3])
        : "r"(a[0]), "r"(a[1]), "r"(a[2]), "r"(a[3]),
          "r"(b[0]), "r"(b[1]));
}

// ---------------------------------------------------------------------------
// Fused permute+round (z=0..2: A operands; z=3..6: weights).
// ---------------------------------------------------------------------------
__global__ __launch_bounds__(256)
void perm_all_kernel(const float* __restrict__ s0, float* __restrict__ d0,
                     const float* __restrict__ s1, float* __restrict__ d1,
                     const float* __restrict__ s2, float* __restrict__ d2,
                     const float* __restrict__ w0, float* __restrict__ p0,
                     const float* __restrict__ w1, float* __restrict__ p1,
                     const float* __restrict__ w2, float* __restrict__ p2,
                     const float* __restrict__ w3, float* __restrict__ p3) {
    const int z = blockIdx.z;
    if (z < 3) {
        const float* src = (z == 0) ? s0 : (z == 1) ? s1 : s2;
        float*       dst = (z == 0) ? d0 : (z == 1) ? d1 : d2;
        const int idx = blockIdx.x * 256 + threadIdx.x;
        const int row = idx >> 6, ch = idx & 63;
        const float4* s = (const float4*)(src + (size_t)row * DM + ch * 16);
        float4 u0 = s[0], u1 = s[1], u2 = s[2], u3 = s[3];
        float vv[16] = { u0.x,u0.y,u0.z,u0.w, u1.x,u1.y,u1.z,u1.w,
                         u2.x,u2.y,u2.z,u2.w, u3.x,u3.y,u3.z,u3.w };
        const int xa = (row >> 1) & 3;
        float4* d = (float4*)(dst + (size_t)row * DM + ch * 16);
#pragma unroll
        for (int x = 0; x < 4; x++) {
            const int kq = x ^ xa;
            float4 o;
            o.x = rndf(vv[kq]); o.y = rndf(vv[kq + 4]);
            o.z = rndf(vv[kq + 8]); o.w = rndf(vv[kq + 12]);
            d[x] = o;
        }
    } else {
        if (blockIdx.x >= 256) return;
        const int zi = z - 3;
        const float* W = (zi == 0) ? w0 : (zi == 1) ? w1 : (zi == 2) ? w2 : w3;
        float*       P = (zi == 0) ? p0 : (zi == 1) ? p1 : (zi == 2) ? p2 : p3;
        const int idx = blockIdx.x * 256 + threadIdx.x;
        const int kt = idx >> 10, n = idx & 1023;
        float out[16];
#pragma unroll
        for (int k = 0; k < 16; k++)
            out[((k & 3) << 2) + (k >> 2)] = rndf(W[(size_t)(kt * 16 + k) * DM + n]);
        float4* d = (float4*)(P + (size_t)kt * (DM * 16) + (size_t)n * 16);
#pragma unroll
        for (int x = 0; x < 4; x++)
            d[x] = make_float4(out[4 * x], out[4 * x + 1], out[4 * x + 2], out[4 * x + 3]);
    }
}

// ---------------------------------------------------------------------------
// GEMM v5 (fused): C = Ap * Wp^T, z selects operand triple. 128x128 tile,
// BK=16, 256 thr = 8 warps (2M x 4N), warp tile 64x32, cp.async 3-stage.
// ---------------------------------------------------------------------------
#define STG 16384
#define GEMM_SMEM (3 * STG)

__device__ __forceinline__ void gemm_issue(uint32_t sb, int s, int t,
                                           const float* Arow, const float* Bkt) {
    const uint32_t ab = sb + s * STG;
    const uint32_t bb = ab + 8192;
#pragma unroll
    for (int i = 0; i < 2; i++) {
        const int ch = t + (i << 8);
        cp16(ab + ch * 16, Arow + (size_t)(ch >> 2) * DM + (ch & 3) * 4);
        cp16(bb + ch * 16, Bkt + ch * 4);
    }
    asm volatile("cp.async.commit_group;" ::: "memory");
}

__global__ void __launch_bounds__(256, 2)
gemm_v5_kernel(const float* __restrict__ A0, const float* __restrict__ W0, float* __restrict__ C0,
               const float* __restrict__ A1, const float* __restrict__ W1, float* __restrict__ C1,
               const float* __restrict__ A2, const float* __restrict__ W2, float* __restrict__ C2) {
    extern __shared__ char sm[];
    const float* Ap = (blockIdx.z == 0) ? A0 : (blockIdx.z == 1) ? A1 : A2;
    const float* Wp = (blockIdx.z == 0) ? W0 : (blockIdx.z == 1) ? W1 : W2;
    float*       C  = (blockIdx.z == 0) ? C0 : (blockIdx.z == 1) ? C1 : C2;

    const uint32_t sb = smem_u32(sm);
    const int t = threadIdx.x, lane = t & 31, warp = t >> 5;
    const int wr = warp >> 2, wc = warp & 3;
    const int bm = blockIdx.y * 128, bn = blockIdx.x * 128;

    const float* Abase = Ap + (size_t)bm * DM;
    const float* Bbase = Wp + (size_t)bn * 16;

    float acc[4][4][4];
#pragma unroll
    for (int mi = 0; mi < 4; mi++)
#pragma unroll
        for (int ni = 0; ni < 4; ni++)
#pragma unroll
            for (int e = 0; e < 4; e++) acc[mi][ni][e] = 0.f;

    gemm_issue(sb, 0, t, Abase, Bbase);
    gemm_issue(sb, 1, t, Abase + 16, Bbase + (size_t)DM * 16);

    const int NT = 64;
#pragma unroll 1
    for (int kt = 0; kt < NT; kt++) {
        const int s = kt - (kt / 3) * 3;
        if (kt < NT - 1) asm volatile("cp.async.wait_group 1;" ::: "memory");
        else             asm volatile("cp.async.wait_group 0;" ::: "memory");
        __syncthreads();

        const float4* as4 = (const float4*)(sm + s * STG);
        const float4* bs4 = (const float4*)(sm + s * STG + 8192);

        float4 bq[4];
        {
            const int c0 = wc * 32 + (lane >> 2);
            const int g = lane & 3;
#pragma unroll
            for (int ni = 0; ni < 4; ni++)
                bq[ni] = bs4[(c0 + ni * 8) * 4 + g];
        }
#pragma unroll
        for (int mi = 0; mi < 4; mi++) {
            const int rlo = wr * 64 + mi * 16 + (lane >> 2);
            const int rhi = rlo + 8;
            float4 alo = as4[rlo * 4 + (((lane & 3) ^ (rlo >> 1)) & 3)];
            float4 ahi = as4[rhi * 4 + (((lane & 3) ^ (rhi >> 1)) & 3)];
            uint32_t a0[4] = { __float_as_uint(alo.x), __float_as_uint(ahi.x),
                               __float_as_uint(alo.y), __float_as_uint(ahi.y) };
            uint32_t a1[4] = { __float_as_uint(alo.z), __float_as_uint(ahi.z),
                               __float_as_uint(alo.w), __float_as_uint(ahi.w) };
#pragma unroll
            for (int ni = 0; ni < 4; ni++) {
                uint32_t b0[2] = { __float_as_uint(bq[ni].x), __float_as_uint(bq[ni].y) };
                uint32_t b1[2] = { __float_as_uint(bq[ni].z), __float_as_uint(bq[ni].w) };
                mma_tf32(acc[mi][ni], a0, b0);
                mma_tf32(acc[mi][ni], a1, b1);
            }
        }

        if (kt + 2 < NT) {
            const int ns = (kt + 2) - ((kt + 2) / 3) * 3;
            gemm_issue(sb, ns, t, Abase + (kt + 2) * 16, Bbase + (size_t)(kt + 2) * DM * 16);
        }
    }

#pragma unroll
    for (int mi = 0; mi < 4; mi++) {
#pragma unroll
        for (int ni = 0; ni < 4; ni++) {
            const int r = bm + wr * 64 + mi * 16 + (lane >> 2);
            const int c = bn + wc * 32 + ni * 8 + ((lane & 3) << 1);
            float2 v0 = make_float2(acc[mi][ni][0], acc[mi][ni][1]);
            float2 v1 = make_float2(acc[mi][ni][2], acc[mi][ni][3]);
            *(float2*)(C + (size_t)r * DM + c) = v0;
            *(float2*)(C + (size_t)(r + 8) * DM + c) = v1;
        }
    }
}

// ---------------------------------------------------------------------------
// Sparse attention v4. Changes vs round 10:
//  - QK split: window lanes pure LDS.128 from padded sK; random lanes pure LDG.
//  - P.V split: window part reads sV (float2, only prob shuffled); random part
//    shuffles (prob,row) and does coalesced float2 LDG.
//  - Output written directly in the GEMM's permuted+tf32-rounded layout
//    (pos = ((k&3)^xa)*4 + (k>>2) within each 16-chunk) -> perm_attn deleted.
// ---------------------------------------------------------------------------
#define TQ 8
#define WROWS 30
#define WPAD 132

__global__ __launch_bounds__(512)
void sparse_attn_kernel(const float* __restrict__ qb, const float* __restrict__ kb,
                        const float* __restrict__ vb, const void* __restrict__ idxp,
                        float* __restrict__ obp) {
    __shared__ float sQ[TQ][128];
    __shared__ float sK[WROWS][WPAD];
    __shared__ float sV[WROWS][WPAD];

    const int t = threadIdx.x;
    const int pbase = blockIdx.x * TQ + 1;
    const int hb = blockIdx.y * 128;
    const int r0 = pbase - 11;

    if (t < 256) {
        int row = t >> 5, i = (t & 31) << 2;
        int p = pbase + row;
        if (p <= SEQ - 2)
            *(float4*)&sQ[row][i] = *(const float4*)(qb + (size_t)p * DM + hb + i);
    }
#pragma unroll
    for (int f = 0; f < 2 * WROWS * 32; f += 512) {
        int g = f + t;
        if (g < 2 * WROWS * 32) {
            int sel = (g >= WROWS * 32);
            int rem = sel ? g - WROWS * 32 : g;
            int row = rem >> 5, i = (rem & 31) << 2;
            int rg = r0 + row;
            rg = rg < 0 ? 0 : (rg > SEQ - 1 ? SEQ - 1 : rg);
            const float* src = (sel ? vb : kb) + (size_t)rg * DM + hb + i;
            float* dst = (sel ? &sV[0][0] : &sK[0][0]) + row * WPAD + i;
            *(float4*)dst = *(const float4*)src;
        }
    }
    __syncthreads();

    const int warp = t >> 5, lane = t & 31;
    const int ql = warp & 7, hl = warp >> 3;
    const int p = pbase + ql;
    if (p > SEQ - 2) return;
    const int n = p - 1;
    const int hdim = hb + hl * 64;

    const float4* qp4 = (const float4*)&sQ[ql][hl * 64];

    // ---- logits (split by lane class) ----
    int row = 0;
    float logit;
    if (lane >= 9) {
        const float4* kp4 = (const float4*)&sK[ql + lane - 9][hl * 64];
        float a = 0.f;
#pragma unroll
        for (int c = 0; c < 16; c++) {
            float4 kv = kp4[c];
            float4 qv = qp4[c];
            a += kv.x * qv.x + kv.y * qv.y + kv.z * qv.z + kv.w * qv.w;
        }
        logit = a * 0.125f;
    } else {
        if (lane >= 1) {
            row = g_idx_is64
                ? (int)((const long long*)idxp)[(size_t)n * NKEY + lane]
                : ((const int*)idxp)[(size_t)n * NKEY + lane];
        }
        const float4* kp4 = (const float4*)(kb + (size_t)row * DM + hdim);
        float a = 0.f;
#pragma unroll
        for (int c = 0; c < 16; c++) {
            float4 kv = kp4[c];
            float4 qv = qp4[c];
            a += kv.x * qv.x + kv.y * qv.y + kv.z * qv.z + kv.w * qv.w;
        }
        logit = a * 0.125f;
    }

    // ---- warp softmax over 32 keys ----
    float m = logit;
#pragma unroll
    for (int o = 16; o > 0; o >>= 1) m = fmaxf(m, __shfl_xor_sync(0xFFFFFFFFu, m, o));
    float e = __expf(logit - m);
    float s = e;
#pragma unroll
    for (int o = 16; o > 0; o >>= 1) s += __shfl_xor_sync(0xFFFFFFFFu, s, o);
    const float prob = e / s;

    // ---- P.V (split): lane covers dims 2*lane, 2*lane+1 ----
    float o0 = 0.f, o1 = 0.f;
#pragma unroll
    for (int j = 9; j < 32; j++) {
        float pj = __shfl_sync(0xFFFFFFFFu, prob, j);
        float2 vv = *(const float2*)&sV[ql + j - 9][hl * 64 + 2 * lane];
        o0 += pj * vv.x;
        o1 += pj * vv.y;
    }
#pragma unroll
    for (int j = 0; j < 9; j++) {
        float pj = __shfl_sync(0xFFFFFFFFu, prob, j);
        int rj = __shfl_sync(0xFFFFFFFFu, row, j);
        float2 vv = *(const float2*)(vb + (size_t)rj * DM + hdim + 2 * lane);
        o0 += pj * vv.x;
        o1 += pj * vv.y;
    }

    // ---- permuted + rounded store ----
    const int xa = (p >> 1) & 3;
    const int d0 = 2 * lane;            // even, so d0 and d0+1 share a 16-chunk
    const int k0 = d0 & 15;
    const int base = d0 & ~15;
    const int pos0 = (((k0 & 3) ^ xa) << 2) | (k0 >> 2);
    const int pos1 = ((((k0 + 1) & 3) ^ xa) << 2) | ((k0 + 1) >> 2);
    float* ob = obp + (size_t)p * DM + hdim + base;
    ob[pos0] = rndf(o0);
    ob[pos1] = rndf(o1);
}

// ---------------------------------------------------------------------------
// Global attention, split-KV (proven ~24 us). Merge writes permuted+rounded.
// ---------------------------------------------------------------------------
__global__ __launch_bounds__(128)
void global_attn_part_kernel(const float* __restrict__ qb, const float* __restrict__ kb,
                             const float* __restrict__ vb) {
    __shared__ float qsh[HD];
    __shared__ float le[128];
    __shared__ float red[128];

    const int c = blockIdx.x;
    const int ph = blockIdx.y;
    const int h = ph & (NH - 1);
    const int p = (ph >> 4) ? (SEQ - 1) : 0;
    const int t = threadIdx.x;
    const int j0 = c * 128;

    if (t < HD / 4)
        ((float4*)qsh)[t] = *(const float4*)(qb + (size_t)p * DM + h * HD + t * 4);
    __syncthreads();

    const float* kr = kb + (size_t)(j0 + t) * DM + h * HD;
    float a = 0.f;
#pragma unroll
    for (int cc = 0; cc < 16; cc++) {
        float4 kv = ((const float4*)kr)[cc];
        float4 qv = ((const float4*)qsh)[cc];
        a += kv.x * qv.x + kv.y * qv.y + kv.z * qv.z + kv.w * qv.w;
    }
    float logit = a * 0.125f;

    red[t] = logit; __syncthreads();
#pragma unroll
    for (int o = 64; o > 0; o >>= 1) {
        if (t < o) red[t] = fmaxf(red[t], red[t + o]);
        __syncthreads();
    }
    const float m = red[0];
    __syncthreads();

    float e = __expf(logit - m);
    le[t] = e;
    red[t] = e; __syncthreads();
#pragma unroll
    for (int o = 64; o > 0; o >>= 1) {
        if (t < o) red[t] += red[t + o];
        __syncthreads();
    }
    const float s = red[0];
    __syncthreads();

    const int d = t & (HD - 1);
    const int half = t >> 6;
    float o = 0.f;
#pragma unroll 4
    for (int j = half * 64; j < half * 64 + 64; j++)
        o += le[j] * vb[(size_t)(j0 + j) * DM + h * HD + d];
    red[t] = o; __syncthreads();
    if (t < HD)
        g_po[ph][c][t] = red[t] + red[t + 64];
    if (t == 0) { g_pm[ph][c] = m; g_ps[ph][c] = s; }
}

__global__ __launch_bounds__(64)
void global_attn_merge_kernel(float* __restrict__ obp) {
    const int ph = blockIdx.x;
    const int h = ph & (NH - 1);
    const int p = (ph >> 4) ? (SEQ - 1) : 0;
    const int t = threadIdx.x;

    float M = -1e30f;
#pragma unroll
    for (int i = 0; i < GCH; i++) M = fmaxf(M, g_pm[ph][i]);
    float S = 0.f, O = 0.f;
#pragma unroll
    for (int i = 0; i < GCH; i++) {
        float w = __expf(g_pm[ph][i] - M);
        S += w * g_ps[ph][i];
        O += w * g_po[ph][i][t];
    }
    // permuted + rounded store
    const int xa = (p >> 1) & 3;
    const int kk = t & 15;
    const int pos = (((kk & 3) ^ xa) << 2) | (kk >> 2);
    obp[(size_t)p * DM + h * HD + (t & ~15) + pos] = rndf(O / S);
}

// ---------------------------------------------------------------------------
// Launch. ncu profiles the 4th launch -> sparse_attn_kernel.
// ---------------------------------------------------------------------------
extern "C" void kernel_launch(void* const* d_in, const int* in_sizes, int n_in,
                              void* d_out, int out_size) {
    const float* Q  = (const float*)d_in[0];
    const float* K  = (const float*)d_in[1];
    const float* V  = (const float*)d_in[2];
    const float* Wq = (const float*)d_in[3];
    const float* Wk = (const float*)d_in[4];
    const float* Wv = (const float*)d_in[5];
    const float* Wo = (const float*)d_in[6];
    const void*  idx = d_in[7];
    float* out = (float*)d_out;

    float *q, *k, *v, *qp, *kp, *vp, *attnp, *wqp, *wkp, *wvp, *wop;
    cudaGetSymbolAddress((void**)&q,     g_q);
    cudaGetSymbolAddress((void**)&k,     g_k);
    cudaGetSymbolAddress((void**)&v,     g_v);
    cudaGetSymbolAddress((void**)&qp,    g_qp);
    cudaGetSymbolAddress((void**)&kp,    g_kp);
    cudaGetSymbolAddress((void**)&vp,    g_vp);
    cudaGetSymbolAddress((void**)&attnp, g_attnp);
    cudaGetSymbolAddress((void**)&wqp,   g_wqp);
    cudaGetSymbolAddress((void**)&wkp,   g_wkp);
    cudaGetSymbolAddress((void**)&wvp,   g_wvp);
    cudaGetSymbolAddress((void**)&wop,   g_wop);

    cudaFuncSetAttribute(gemm_v5_kernel, cudaFuncAttributeMaxDynamicSharedMemorySize, GEMM_SMEM);

    detect_idx_kernel<<<1, 1>>>((const int*)idx);                              // 1

    dim3 gp(1024, 1, 7);
    perm_all_kernel<<<gp, 256>>>(Q, qp, K, kp, V, vp,
                                 Wq, wqp, Wk, wkp, Wv, wvp, Wo, wop);          // 2

    dim3 gg(8, 32, 3);
    gemm_v5_kernel<<<gg, 256, GEMM_SMEM>>>(qp, wqp, q, kp, wkp, k, vp, wvp, v); // 3

    dim3 gsp((NNG + TQ - 1) / TQ, NH / 2);
    sparse_attn_kernel<<<gsp, 512>>>(q, k, v, idx, attnp);                     // 4 (profiled)

    dim3 gga(GCH, 32);
    global_attn_part_kernel<<<gga, 128>>>(q, k, v);                            // 5
    global_attn_merge_kernel<<<32, 64>>>(attnp);                               // 6

    dim3 go(8, 32, 1);
    gemm_v5_kernel<<<go, 256, GEMM_SMEM>>>(attnp, wop, out,
                                           attnp, wop, out, attnp, wop, out);  // 7
}